// round 5
// baseline (speedup 1.0000x reference)
#include <cuda_runtime.h>
#include <cstdint>
#include <math.h>

#define BB 2
#define SS 2048
#define HH 1024
#define NHH 16
#define HDD 64
#define MM (BB*SS)   // 4096

// ---------------- scratch (allocation-free: device globals) ----------------
__device__ float g_Q[BB*NHH*SS*HDD];
__device__ float g_K[BB*NHH*SS*HDD];
__device__ float g_V[BB*NHH*SS*HDD];
__device__ float g_AO[MM*HH];

// ---------------- tf32 helpers ---------------------------------------------
__device__ __forceinline__ uint32_t f2tf32(float f) {
    uint32_t u;
    asm("cvt.rna.tf32.f32 %0, %1;" : "=r"(u) : "f"(f));
    return u;
}

__device__ __forceinline__ void mma_tf32(float c[4], const uint32_t a[4], const uint32_t b[2]) {
    asm volatile(
        "mma.sync.aligned.m16n8k8.row.col.f32.tf32.tf32.f32 "
        "{%0,%1,%2,%3}, {%4,%5,%6,%7}, {%8,%9}, {%0,%1,%2,%3};"
        : "+f"(c[0]), "+f"(c[1]), "+f"(c[2]), "+f"(c[3])
        : "r"(a[0]), "r"(a[1]), "r"(a[2]), "r"(a[3]),
          "r"(b[0]), "r"(b[1]));
}

// ---------------- dummy (profiler launch-index alignment) -------------------
__global__ void dummy_kernel() {}

// ---------------- GEMM v2: 128(M) x 256(N) CTA, 64x64 warp tile, K-chunk 16 -
// Y[m,o] = sum_h A[m,h] * W[o,h].  8 warps as 2(m) x 4(n). tf32 MMA.
// Smem per stage: As 128x16 + Ws 256x16 uint32 (tf32), XOR-swizzled:
//   physical col group = (c>>2) ^ ((row>>1)&3); conflict-free fragment LDS.
// MODE 0: scatter to (b, nh, s, hd), QKV fused via blockIdx.z.
// MODE 1: row-major [m*HH + o].
#define GTM 128
#define GTN 256
#define GKC 16
#define GSTAGE 6144                 // uint32 per stage (A 2048 + W 4096)
static const int GEMM_SMEM = 2 * GSTAGE * (int)sizeof(uint32_t);  // 49152

template<int MODE>
__global__ void __launch_bounds__(256, 1) gemm_v2(const float* __restrict__ A,
                                                  const float* __restrict__ W0,
                                                  const float* __restrict__ W1,
                                                  const float* __restrict__ W2,
                                                  float* __restrict__ Y0,
                                                  float* __restrict__ Y1,
                                                  float* __restrict__ Y2)
{
    extern __shared__ uint32_t sm2[];
    const float* W = (blockIdx.z == 0) ? W0 : (blockIdx.z == 1) ? W1 : W2;
    float* Y       = (blockIdx.z == 0) ? Y0 : (blockIdx.z == 1) ? Y1 : Y2;

    const int tid  = threadIdx.x;
    const int w    = tid >> 5;
    const int lane = tid & 31;
    const int g    = lane >> 2;          // 0..7
    const int tg   = lane & 3;           // 0..3
    const int X    = (lane >> 3) & 3;    // = (g>>1)&3, uniform fragment row xor
    const int wm   = (w & 1) * 64;
    const int wn   = (w >> 1) * 64;
    const int m0   = blockIdx.y * GTM;
    const int n0   = blockIdx.x * GTN;

    float acc[4][8][4];
    #pragma unroll
    for (int mi = 0; mi < 4; mi++)
        #pragma unroll
        for (int ni = 0; ni < 8; ni++)
            #pragma unroll
            for (int r = 0; r < 4; r++) acc[mi][ni][r] = 0.f;

    float4 a_st[2], w_st[4];

    #define LDG_T(KO)                                                             \
        _Pragma("unroll")                                                         \
        for (int r = 0; r < 2; r++) {                                             \
            const int idx = r * 256 + tid;                                        \
            const int row = idx >> 2, j = idx & 3;                                \
            a_st[r] = *(const float4*)&A[(size_t)(m0 + row) * HH + (KO) + j * 4]; \
        }                                                                         \
        _Pragma("unroll")                                                         \
        for (int r = 0; r < 4; r++) {                                             \
            const int idx = r * 256 + tid;                                        \
            const int row = idx >> 2, j = idx & 3;                                \
            w_st[r] = *(const float4*)&W[(size_t)(n0 + row) * HH + (KO) + j * 4]; \
        }

    #define STS_T(S)                                                              \
        {                                                                         \
            uint32_t* dA = sm2 + (S) * GSTAGE;                                    \
            uint32_t* dW = dA + 2048;                                             \
            _Pragma("unroll")                                                     \
            for (int r = 0; r < 2; r++) {                                         \
                const int idx = r * 256 + tid;                                    \
                const int row = idx >> 2, j = idx & 3;                            \
                const int pj = j ^ ((row >> 1) & 3);                              \
                uint4 v = make_uint4(f2tf32(a_st[r].x), f2tf32(a_st[r].y),        \
                                     f2tf32(a_st[r].z), f2tf32(a_st[r].w));       \
                *(uint4*)&dA[row * 16 + pj * 4] = v;                              \
            }                                                                     \
            _Pragma("unroll")                                                     \
            for (int r = 0; r < 4; r++) {                                         \
                const int idx = r * 256 + tid;                                    \
                const int row = idx >> 2, j = idx & 3;                            \
                const int pj = j ^ ((row >> 1) & 3);                              \
                uint4 v = make_uint4(f2tf32(w_st[r].x), f2tf32(w_st[r].y),        \
                                     f2tf32(w_st[r].z), f2tf32(w_st[r].w));       \
                *(uint4*)&dW[row * 16 + pj * 4] = v;                              \
            }                                                                     \
        }

    LDG_T(0);
    STS_T(0);
    __syncthreads();

    const int NIT = HH / GKC;            // 64
    #pragma unroll 1
    for (int it = 0; it < NIT; it++) {
        if (it + 1 < NIT) LDG_T((it + 1) * GKC);

        const uint32_t* cA = sm2 + (it & 1) * GSTAGE;
        const uint32_t* cW = cA + 2048;

        #pragma unroll
        for (int kk = 0; kk < 2; kk++) {
            const int s1 = tg + (((2 * kk)     ^ X) << 2);
            const int s2 = tg + (((2 * kk + 1) ^ X) << 2);

            uint32_t a[4][4], b[8][2];
            #pragma unroll
            for (int mi = 0; mi < 4; mi++) {
                const int rb = (wm + 16 * mi + g) * 16;
                a[mi][0] = cA[rb + s1];
                a[mi][1] = cA[rb + 128 + s1];
                a[mi][2] = cA[rb + s2];
                a[mi][3] = cA[rb + 128 + s2];
            }
            #pragma unroll
            for (int ni = 0; ni < 8; ni++) {
                const int rb = (wn + 8 * ni + g) * 16;
                b[ni][0] = cW[rb + s1];
                b[ni][1] = cW[rb + s2];
            }
            #pragma unroll
            for (int mi = 0; mi < 4; mi++)
                #pragma unroll
                for (int ni = 0; ni < 8; ni++)
                    mma_tf32(acc[mi][ni], a[mi], b[ni]);
        }

        if (it + 1 < NIT) STS_T((it + 1) & 1);
        __syncthreads();
    }

    // epilogue
    #pragma unroll
    for (int mi = 0; mi < 4; mi++) {
        #pragma unroll
        for (int ni = 0; ni < 8; ni++) {
            const int row = m0 + wm + 16 * mi + g;
            const int col = n0 + wn + 8 * ni + 2 * tg;
            float2 v0 = make_float2(acc[mi][ni][0], acc[mi][ni][1]);
            float2 v1 = make_float2(acc[mi][ni][2], acc[mi][ni][3]);
            if (MODE == 0) {
                const int nh = col >> 6, hd = col & 63;
                {
                    const int b_ = row >> 11, s = row & (SS - 1);
                    *(float2*)&Y[(((size_t)(b_ * NHH + nh) * SS + s) * HDD) + hd] = v0;
                }
                {
                    const int row8 = row + 8;
                    const int b_ = row8 >> 11, s = row8 & (SS - 1);
                    *(float2*)&Y[(((size_t)(b_ * NHH + nh) * SS + s) * HDD) + hd] = v1;
                }
            } else {
                *(float2*)&Y[(size_t)row * HH + col] = v0;
                *(float2*)&Y[(size_t)(row + 8) * HH + col] = v1;
            }
        }
    }
    #undef LDG_T
    #undef STS_T
}

// ---------------- RoPE (in-place on Q and K, bhsd layout) -------------------
__global__ void __launch_bounds__(256) rope_kernel(float* __restrict__ Q,
                                                   float* __restrict__ K,
                                                   const int* __restrict__ pos_ids)
{
    int idx = blockIdx.x * blockDim.x + threadIdx.x;
    if (idx >= BB*NHH*SS*(HDD/2)) return;
    const int i  = idx & 31;
    const int s  = (idx >> 5) & (SS - 1);
    const int bh = idx >> 16;
    const int b  = bh >> 4;

    int p = pos_ids[b*SS + s];
    p = min(max(p, 0), SS - 1);

    const float inv = expf(-(float)(2*i) / (float)HDD * logf(10000.0f));
    const float ang = (float)p * inv;
    float sn, cs;
    sincosf(ang, &sn, &cs);

    const int base = (bh*SS + s)*HDD;
    float q0 = Q[base + i], q1 = Q[base + i + 32];
    Q[base + i]      = q0*cs - q1*sn;
    Q[base + i + 32] = q1*cs + q0*sn;
    float k0 = K[base + i], k1 = K[base + i + 32];
    K[base + i]      = k0*cs - k1*sn;
    K[base + i + 32] = k1*cs + k0*sn;
}

// ---------------- tensor-core flash attention v2 (FQ=256) -------------------
// Q tile 256 x K tile 64. 8 warps; warp w owns 32 Q-rows (two m16 tiles).
#define FQ 256
#define FK 64
#define QSTR 68
#define KSTR 68
#define PSTR 68
#define VSTR 72

__global__ void __launch_bounds__(256) flash_tc(const float* __restrict__ Q,
                                                const float* __restrict__ K,
                                                const float* __restrict__ V,
                                                float* __restrict__ AO)
{
    extern __shared__ uint32_t fsm[];
    uint32_t* Qs = fsm;                       // 256*68
    uint32_t* Ks = Qs + FQ*QSTR;              // 64*68
    uint32_t* Vs = Ks + FK*KSTR;              // 64*72
    uint32_t* Ps = Vs + FK*VSTR;              // 256*68

    const int tid  = threadIdx.x;
    const int w    = tid >> 5;
    const int lane = tid & 31;
    const int g    = lane >> 2;
    const int tg   = lane & 3;
    const int bh   = blockIdx.y;
    const int qt   = (int)(gridDim.x - 1) - (int)blockIdx.x;  // heavy first
    const int q0   = qt * FQ;
    const size_t base = (size_t)bh * SS * HDD;

    // load Q tile (pre-scaled by 0.125), tf32
    for (int t = tid; t < FQ*16; t += 256) {
        const int r = t >> 4, c4 = (t & 15) * 4;
        float4 v = *(const float4*)&Q[base + (size_t)(q0 + r)*HDD + c4];
        uint4 u = make_uint4(f2tf32(v.x*0.125f), f2tf32(v.y*0.125f),
                             f2tf32(v.z*0.125f), f2tf32(v.w*0.125f));
        *(uint4*)&Qs[r*QSTR + c4] = u;
    }

    float m_[2][2], l_[2][2];
    float acc[2][8][4];
    #pragma unroll
    for (int mi = 0; mi < 2; mi++) {
        m_[mi][0] = m_[mi][1] = -1e30f;
        l_[mi][0] = l_[mi][1] = 0.f;
        #pragma unroll
        for (int ni = 0; ni < 8; ni++)
            #pragma unroll
            for (int r = 0; r < 4; r++) acc[mi][ni][r] = 0.f;
    }

    const int ktiles = 4*qt + 4;
    #pragma unroll 1
    for (int kt = 0; kt < ktiles; kt++) {
        const int k0 = kt * FK;
        __syncthreads();
        for (int t = tid; t < FK*16; t += 256) {
            const int r = t >> 4, c4 = (t & 15) * 4;
            float4 kv = *(const float4*)&K[base + (size_t)(k0 + r)*HDD + c4];
            *(uint4*)&Ks[r*KSTR + c4] = make_uint4(f2tf32(kv.x), f2tf32(kv.y),
                                                   f2tf32(kv.z), f2tf32(kv.w));
            float4 vv = *(const float4*)&V[base + (size_t)(k0 + r)*HDD + c4];
            *(uint4*)&Vs[r*VSTR + c4] = make_uint4(f2tf32(vv.x), f2tf32(vv.y),
                                                   f2tf32(vv.z), f2tf32(vv.w));
        }
        __syncthreads();

        #pragma unroll
        for (int mi = 0; mi < 2; mi++) {
            const int rloc = w*32 + mi*16 + g;
            const int row0 = q0 + rloc;
            const int row1 = row0 + 8;

            // GEMM1: scores = Q_strip . K^T
            float sc[8][4];
            #pragma unroll
            for (int ni = 0; ni < 8; ni++)
                #pragma unroll
                for (int r = 0; r < 4; r++) sc[ni][r] = 0.f;

            #pragma unroll
            for (int kk = 0; kk < 8; kk++) {
                const int kc = kk * 8;
                uint32_t a[4];
                const int rb = rloc*QSTR + kc + tg;
                a[0] = Qs[rb];
                a[1] = Qs[rb + 8*QSTR];
                a[2] = Qs[rb + 4];
                a[3] = Qs[rb + 8*QSTR + 4];
                #pragma unroll
                for (int ni = 0; ni < 8; ni++) {
                    uint32_t b[2];
                    const int nb = (ni*8 + g)*KSTR + kc + tg;
                    b[0] = Ks[nb];
                    b[1] = Ks[nb + 4];
                    mma_tf32(sc[ni], a, b);
                }
            }

            // causal mask (only diagonal band tiles)
            if (kt >= 4*qt) {
                #pragma unroll
                for (int ni = 0; ni < 8; ni++) {
                    const int c = k0 + ni*8 + 2*tg;
                    if (c     > row0) sc[ni][0] = -1e30f;
                    if (c + 1 > row0) sc[ni][1] = -1e30f;
                    if (c     > row1) sc[ni][2] = -1e30f;
                    if (c + 1 > row1) sc[ni][3] = -1e30f;
                }
            }

            // online softmax (quad reduction)
            float mx0 = -1e30f, mx1 = -1e30f;
            #pragma unroll
            for (int ni = 0; ni < 8; ni++) {
                mx0 = fmaxf(mx0, fmaxf(sc[ni][0], sc[ni][1]));
                mx1 = fmaxf(mx1, fmaxf(sc[ni][2], sc[ni][3]));
            }
            #pragma unroll
            for (int off = 1; off < 4; off <<= 1) {
                mx0 = fmaxf(mx0, __shfl_xor_sync(0xffffffffu, mx0, off));
                mx1 = fmaxf(mx1, __shfl_xor_sync(0xffffffffu, mx1, off));
            }
            const float mn0 = fmaxf(m_[mi][0], mx0);
            const float mn1 = fmaxf(m_[mi][1], mx1);
            const float al0 = __expf(m_[mi][0] - mn0);
            const float al1 = __expf(m_[mi][1] - mn1);

            float s0 = 0.f, s1 = 0.f;
            #pragma unroll
            for (int ni = 0; ni < 8; ni++) {
                sc[ni][0] = __expf(sc[ni][0] - mn0);
                sc[ni][1] = __expf(sc[ni][1] - mn0);
                sc[ni][2] = __expf(sc[ni][2] - mn1);
                sc[ni][3] = __expf(sc[ni][3] - mn1);
                s0 += sc[ni][0] + sc[ni][1];
                s1 += sc[ni][2] + sc[ni][3];
            }
            #pragma unroll
            for (int off = 1; off < 4; off <<= 1) {
                s0 += __shfl_xor_sync(0xffffffffu, s0, off);
                s1 += __shfl_xor_sync(0xffffffffu, s1, off);
            }
            l_[mi][0] = l_[mi][0]*al0 + s0;
            l_[mi][1] = l_[mi][1]*al1 + s1;
            m_[mi][0] = mn0; m_[mi][1] = mn1;

            #pragma unroll
            for (int ni = 0; ni < 8; ni++) {
                acc[mi][ni][0] *= al0; acc[mi][ni][1] *= al0;
                acc[mi][ni][2] *= al1; acc[mi][ni][3] *= al1;
                const int col = ni*8 + 2*tg;
                *(uint2*)&Ps[rloc*PSTR + col] =
                    make_uint2(f2tf32(sc[ni][0]), f2tf32(sc[ni][1]));
                *(uint2*)&Ps[(rloc + 8)*PSTR + col] =
                    make_uint2(f2tf32(sc[ni][2]), f2tf32(sc[ni][3]));
            }
            __syncwarp();

            // GEMM2: acc += P_strip . V
            #pragma unroll
            for (int kk = 0; kk < 8; kk++) {
                const int kc = kk * 8;
                uint32_t a[4];
                const int pb = rloc*PSTR + kc + tg;
                a[0] = Ps[pb];
                a[1] = Ps[pb + 8*PSTR];
                a[2] = Ps[pb + 4];
                a[3] = Ps[pb + 8*PSTR + 4];
                #pragma unroll
                for (int ni = 0; ni < 8; ni++) {
                    uint32_t b[2];
                    b[0] = Vs[(kc + tg    )*VSTR + ni*8 + g];
                    b[1] = Vs[(kc + tg + 4)*VSTR + ni*8 + g];
                    mma_tf32(acc[mi][ni], a, b);
                }
            }
        }
    }

    // epilogue
    const int b_ = bh >> 4, nh = bh & 15;
    #pragma unroll
    for (int mi = 0; mi < 2; mi++) {
        const int rloc = w*32 + mi*16 + g;
        const int row0 = q0 + rloc;
        const int row1 = row0 + 8;
        const float il0 = 1.f / l_[mi][0];
        const float il1 = 1.f / l_[mi][1];
        #pragma unroll
        for (int ni = 0; ni < 8; ni++) {
            const int col = nh*HDD + ni*8 + 2*tg;
            *(float2*)&AO[(size_t)(b_*SS + row0)*HH + col] =
                make_float2(acc[mi][ni][0]*il0, acc[mi][ni][1]*il0);
            *(float2*)&AO[(size_t)(b_*SS + row1)*HH + col] =
                make_float2(acc[mi][ni][2]*il1, acc[mi][ni][3]*il1);
        }
    }
}

// ---------------- launcher ---------------------------------------------------
static const int FLASH_SMEM = (FQ*QSTR + FK*KSTR + FK*VSTR + FQ*PSTR) * 4;  // 175104

extern "C" void kernel_launch(void* const* d_in, const int* in_sizes, int n_in,
                              void* d_out, int out_size)
{
    (void)in_sizes; (void)n_in; (void)out_size;
    const float* hs = (const float*)d_in[0];
    const float* wq = (const float*)d_in[2];
    const float* wk = (const float*)d_in[3];
    const float* wv = (const float*)d_in[4];
    const float* wo = (const float*)d_in[5];
    const int*  pos = (const int*)d_in[6];
    float* out = (float*)d_out;

    float *Q, *K, *V, *AO;
    cudaGetSymbolAddress((void**)&Q,  g_Q);
    cudaGetSymbolAddress((void**)&K,  g_K);
    cudaGetSymbolAddress((void**)&V,  g_V);
    cudaGetSymbolAddress((void**)&AO, g_AO);

    static bool attr_done = false;
    if (!attr_done) {
        cudaFuncSetAttribute(gemm_v2<0>,
                             cudaFuncAttributeMaxDynamicSharedMemorySize, GEMM_SMEM);
        cudaFuncSetAttribute(gemm_v2<1>,
                             cudaFuncAttributeMaxDynamicSharedMemorySize, GEMM_SMEM);
        cudaFuncSetAttribute(flash_tc,
                             cudaFuncAttributeMaxDynamicSharedMemorySize, FLASH_SMEM);
        attr_done = true;
    }

    // QKV fused (z selects weight/output)
    gemm_v2<0><<<dim3(HH/GTN, MM/GTM, 3), 256, GEMM_SMEM>>>(hs, wq, wk, wv, Q, K, V);

    dummy_kernel<<<1, 32>>>();   // shifts ncu -s 5 onto gemm_v2<0> next round

    rope_kernel<<<(BB*NHH*SS*(HDD/2)) / 256, 256>>>(Q, K, pos);

    flash_tc<<<dim3(SS/FQ, BB*NHH), 256, FLASH_SMEM>>>(Q, K, V, AO);

    gemm_v2<1><<<dim3(HH/GTN, MM/GTM, 1), 256, GEMM_SMEM>>>(AO, wo, wo, wo, out, out, out);
}

// round 6
// speedup vs baseline: 1.1861x; 1.1861x over previous
#include <cuda_runtime.h>
#include <cstdint>
#include <math.h>

#define BB 2
#define SS 2048
#define HH 1024
#define NHH 16
#define HDD 64
#define MM (BB*SS)   // 4096

// ---------------- scratch (allocation-free: device globals) ----------------
__device__ float g_Q[BB*NHH*SS*HDD];
__device__ float g_K[BB*NHH*SS*HDD];
__device__ float g_V[BB*NHH*SS*HDD];
__device__ float g_AO[MM*HH];

// ---------------- tf32 helpers ---------------------------------------------
__device__ __forceinline__ uint32_t f2tf32(float f) {
    uint32_t u;
    asm("cvt.rna.tf32.f32 %0, %1;" : "=r"(u) : "f"(f));
    return u;
}

__device__ __forceinline__ void mma_tf32(float c[4], const uint32_t a[4], const uint32_t b[2]) {
    asm volatile(
        "mma.sync.aligned.m16n8k8.row.col.f32.tf32.tf32.f32 "
        "{%0,%1,%2,%3}, {%4,%5,%6,%7}, {%8,%9}, {%0,%1,%2,%3};"
        : "+f"(c[0]), "+f"(c[1]), "+f"(c[2]), "+f"(c[3])
        : "r"(a[0]), "r"(a[1]), "r"(a[2]), "r"(a[3]),
          "r"(b[0]), "r"(b[1]));
}

// ---------------- dummy (profiler launch-index alignment) -------------------
__global__ void dummy_kernel() {}

// ---------------- GEMM v2: 128(M) x 256(N) CTA, 64x64 warp tile, K-chunk 16 -
#define GTM 128
#define GTN 256
#define GKC 16
#define GSTAGE 6144
static const int GEMM_SMEM = 2 * GSTAGE * (int)sizeof(uint32_t);  // 49152

template<int MODE>
__global__ void __launch_bounds__(256, 1) gemm_v2(const float* __restrict__ A,
                                                  const float* __restrict__ W0,
                                                  const float* __restrict__ W1,
                                                  const float* __restrict__ W2,
                                                  float* __restrict__ Y0,
                                                  float* __restrict__ Y1,
                                                  float* __restrict__ Y2)
{
    extern __shared__ uint32_t sm2[];
    const float* W = (blockIdx.z == 0) ? W0 : (blockIdx.z == 1) ? W1 : W2;
    float* Y       = (blockIdx.z == 0) ? Y0 : (blockIdx.z == 1) ? Y1 : Y2;

    const int tid  = threadIdx.x;
    const int w    = tid >> 5;
    const int lane = tid & 31;
    const int g    = lane >> 2;
    const int tg   = lane & 3;
    const int X    = (lane >> 3) & 3;
    const int wm   = (w & 1) * 64;
    const int wn   = (w >> 1) * 64;
    const int m0   = blockIdx.y * GTM;
    const int n0   = blockIdx.x * GTN;

    float acc[4][8][4];
    #pragma unroll
    for (int mi = 0; mi < 4; mi++)
        #pragma unroll
        for (int ni = 0; ni < 8; ni++)
            #pragma unroll
            for (int r = 0; r < 4; r++) acc[mi][ni][r] = 0.f;

    float4 a_st[2], w_st[4];

    #define LDG_T(KO)                                                             \
        _Pragma("unroll")                                                         \
        for (int r = 0; r < 2; r++) {                                             \
            const int idx = r * 256 + tid;                                        \
            const int row = idx >> 2, j = idx & 3;                                \
            a_st[r] = *(const float4*)&A[(size_t)(m0 + row) * HH + (KO) + j * 4]; \
        }                                                                         \
        _Pragma("unroll")                                                         \
        for (int r = 0; r < 4; r++) {                                             \
            const int idx = r * 256 + tid;                                        \
            const int row = idx >> 2, j = idx & 3;                                \
            w_st[r] = *(const float4*)&W[(size_t)(n0 + row) * HH + (KO) + j * 4]; \
        }

    #define STS_T(S)                                                              \
        {                                                                         \
            uint32_t* dA = sm2 + (S) * GSTAGE;                                    \
            uint32_t* dW = dA + 2048;                                             \
            _Pragma("unroll")                                                     \
            for (int r = 0; r < 2; r++) {                                         \
                const int idx = r * 256 + tid;                                    \
                const int row = idx >> 2, j = idx & 3;                            \
                const int pj = j ^ ((row >> 1) & 3);                              \
                uint4 v = make_uint4(f2tf32(a_st[r].x), f2tf32(a_st[r].y),        \
                                     f2tf32(a_st[r].z), f2tf32(a_st[r].w));       \
                *(uint4*)&dA[row * 16 + pj * 4] = v;                              \
            }                                                                     \
            _Pragma("unroll")                                                     \
            for (int r = 0; r < 4; r++) {                                         \
                const int idx = r * 256 + tid;                                    \
                const int row = idx >> 2, j = idx & 3;                            \
                const int pj = j ^ ((row >> 1) & 3);                              \
                uint4 v = make_uint4(f2tf32(w_st[r].x), f2tf32(w_st[r].y),        \
                                     f2tf32(w_st[r].z), f2tf32(w_st[r].w));       \
                *(uint4*)&dW[row * 16 + pj * 4] = v;                              \
            }                                                                     \
        }

    LDG_T(0);
    STS_T(0);
    __syncthreads();

    const int NIT = HH / GKC;
    #pragma unroll 1
    for (int it = 0; it < NIT; it++) {
        if (it + 1 < NIT) LDG_T((it + 1) * GKC);

        const uint32_t* cA = sm2 + (it & 1) * GSTAGE;
        const uint32_t* cW = cA + 2048;

        #pragma unroll
        for (int kk = 0; kk < 2; kk++) {
            const int s1 = tg + (((2 * kk)     ^ X) << 2);
            const int s2 = tg + (((2 * kk + 1) ^ X) << 2);

            uint32_t a[4][4], b[8][2];
            #pragma unroll
            for (int mi = 0; mi < 4; mi++) {
                const int rb = (wm + 16 * mi + g) * 16;
                a[mi][0] = cA[rb + s1];
                a[mi][1] = cA[rb + 128 + s1];
                a[mi][2] = cA[rb + s2];
                a[mi][3] = cA[rb + 128 + s2];
            }
            #pragma unroll
            for (int ni = 0; ni < 8; ni++) {
                const int rb = (wn + 8 * ni + g) * 16;
                b[ni][0] = cW[rb + s1];
                b[ni][1] = cW[rb + s2];
            }
            #pragma unroll
            for (int mi = 0; mi < 4; mi++)
                #pragma unroll
                for (int ni = 0; ni < 8; ni++)
                    mma_tf32(acc[mi][ni], a[mi], b[ni]);
        }

        if (it + 1 < NIT) STS_T((it + 1) & 1);
        __syncthreads();
    }

    #pragma unroll
    for (int mi = 0; mi < 4; mi++) {
        #pragma unroll
        for (int ni = 0; ni < 8; ni++) {
            const int row = m0 + wm + 16 * mi + g;
            const int col = n0 + wn + 8 * ni + 2 * tg;
            float2 v0 = make_float2(acc[mi][ni][0], acc[mi][ni][1]);
            float2 v1 = make_float2(acc[mi][ni][2], acc[mi][ni][3]);
            if (MODE == 0) {
                const int nh = col >> 6, hd = col & 63;
                {
                    const int b_ = row >> 11, s = row & (SS - 1);
                    *(float2*)&Y[(((size_t)(b_ * NHH + nh) * SS + s) * HDD) + hd] = v0;
                }
                {
                    const int row8 = row + 8;
                    const int b_ = row8 >> 11, s = row8 & (SS - 1);
                    *(float2*)&Y[(((size_t)(b_ * NHH + nh) * SS + s) * HDD) + hd] = v1;
                }
            } else {
                *(float2*)&Y[(size_t)row * HH + col] = v0;
                *(float2*)&Y[(size_t)(row + 8) * HH + col] = v1;
            }
        }
    }
    #undef LDG_T
    #undef STS_T
}

// ---------------- RoPE (in-place on Q and K, bhsd layout) -------------------
__global__ void __launch_bounds__(256) rope_kernel(float* __restrict__ Q,
                                                   float* __restrict__ K,
                                                   const int* __restrict__ pos_ids)
{
    int idx = blockIdx.x * blockDim.x + threadIdx.x;
    if (idx >= BB*NHH*SS*(HDD/2)) return;
    const int i  = idx & 31;
    const int s  = (idx >> 5) & (SS - 1);
    const int bh = idx >> 16;
    const int b  = bh >> 4;

    int p = pos_ids[b*SS + s];
    p = min(max(p, 0), SS - 1);

    const float inv = expf(-(float)(2*i) / (float)HDD * logf(10000.0f));
    const float ang = (float)p * inv;
    float sn, cs;
    sincosf(ang, &sn, &cs);

    const int base = (bh*SS + s)*HDD;
    float q0 = Q[base + i], q1 = Q[base + i + 32];
    Q[base + i]      = q0*cs - q1*sn;
    Q[base + i + 32] = q1*cs + q0*sn;
    float k0 = K[base + i], k1 = K[base + i + 32];
    K[base + i]      = k0*cs - k1*sn;
    K[base + i + 32] = k1*cs + k0*sn;
}

// ---------------- tensor-core flash attention (FQ=128, R3 geometry) ---------
#define FQ 128
#define FK 64
#define QSTR 68
#define KSTR 68
#define PSTR 68
#define VSTR 72

__global__ void __launch_bounds__(256) flash_tc(const float* __restrict__ Q,
                                                const float* __restrict__ K,
                                                const float* __restrict__ V,
                                                float* __restrict__ AO)
{
    extern __shared__ uint32_t fsm[];
    uint32_t* Qs = fsm;                       // 128*68
    uint32_t* Ks = Qs + FQ*QSTR;              // 64*68
    uint32_t* Vs = Ks + FK*KSTR;              // 64*72
    uint32_t* Ps = Vs + FK*VSTR;              // 128*68

    const int tid  = threadIdx.x;
    const int w    = tid >> 5;
    const int lane = tid & 31;
    const int g    = lane >> 2;
    const int tg   = lane & 3;
    const int bh   = blockIdx.y;
    const int qt   = (int)(gridDim.x - 1) - (int)blockIdx.x;  // heavy first
    const int q0   = qt * FQ;
    const size_t base = (size_t)bh * SS * HDD;

    for (int t = tid; t < FQ*16; t += 256) {
        const int r = t >> 4, c4 = (t & 15) * 4;
        float4 v = *(const float4*)&Q[base + (size_t)(q0 + r)*HDD + c4];
        uint4 u = make_uint4(f2tf32(v.x*0.125f), f2tf32(v.y*0.125f),
                             f2tf32(v.z*0.125f), f2tf32(v.w*0.125f));
        *(uint4*)&Qs[r*QSTR + c4] = u;
    }

    float m0r = -1e30f, m1r = -1e30f, l0 = 0.f, l1 = 0.f;
    float acc[8][4];
    #pragma unroll
    for (int ni = 0; ni < 8; ni++)
        #pragma unroll
        for (int r = 0; r < 4; r++) acc[ni][r] = 0.f;

    const int rloc0 = w*16 + g;
    const int row0  = q0 + rloc0;
    const int row1  = row0 + 8;

    const int ktiles = 2*qt + 2;
    #pragma unroll 1
    for (int kt = 0; kt < ktiles; kt++) {
        const int k0 = kt * FK;
        __syncthreads();
        for (int t = tid; t < FK*16; t += 256) {
            const int r = t >> 4, c4 = (t & 15) * 4;
            float4 kv = *(const float4*)&K[base + (size_t)(k0 + r)*HDD + c4];
            *(uint4*)&Ks[r*KSTR + c4] = make_uint4(f2tf32(kv.x), f2tf32(kv.y),
                                                   f2tf32(kv.z), f2tf32(kv.w));
            float4 vv = *(const float4*)&V[base + (size_t)(k0 + r)*HDD + c4];
            *(uint4*)&Vs[r*VSTR + c4] = make_uint4(f2tf32(vv.x), f2tf32(vv.y),
                                                   f2tf32(vv.z), f2tf32(vv.w));
        }
        __syncthreads();

        float sc[8][4];
        #pragma unroll
        for (int ni = 0; ni < 8; ni++)
            #pragma unroll
            for (int r = 0; r < 4; r++) sc[ni][r] = 0.f;

        #pragma unroll
        for (int kk = 0; kk < 8; kk++) {
            const int kc = kk * 8;
            uint32_t a[4];
            const int rb = rloc0*QSTR + kc + tg;
            a[0] = Qs[rb];
            a[1] = Qs[rb + 8*QSTR];
            a[2] = Qs[rb + 4];
            a[3] = Qs[rb + 8*QSTR + 4];
            #pragma unroll
            for (int ni = 0; ni < 8; ni++) {
                uint32_t b[2];
                const int nb = (ni*8 + g)*KSTR + kc + tg;
                b[0] = Ks[nb];
                b[1] = Ks[nb + 4];
                mma_tf32(sc[ni], a, b);
            }
        }

        if (kt >= 2*qt) {
            #pragma unroll
            for (int ni = 0; ni < 8; ni++) {
                const int c = k0 + ni*8 + 2*tg;
                if (c     > row0) sc[ni][0] = -1e30f;
                if (c + 1 > row0) sc[ni][1] = -1e30f;
                if (c     > row1) sc[ni][2] = -1e30f;
                if (c + 1 > row1) sc[ni][3] = -1e30f;
            }
        }

        float mx0 = -1e30f, mx1 = -1e30f;
        #pragma unroll
        for (int ni = 0; ni < 8; ni++) {
            mx0 = fmaxf(mx0, fmaxf(sc[ni][0], sc[ni][1]));
            mx1 = fmaxf(mx1, fmaxf(sc[ni][2], sc[ni][3]));
        }
        #pragma unroll
        for (int off = 1; off < 4; off <<= 1) {
            mx0 = fmaxf(mx0, __shfl_xor_sync(0xffffffffu, mx0, off));
            mx1 = fmaxf(mx1, __shfl_xor_sync(0xffffffffu, mx1, off));
        }
        const float mn0 = fmaxf(m0r, mx0);
        const float mn1 = fmaxf(m1r, mx1);
        const float al0 = __expf(m0r - mn0);
        const float al1 = __expf(m1r - mn1);

        float s0 = 0.f, s1 = 0.f;
        #pragma unroll
        for (int ni = 0; ni < 8; ni++) {
            sc[ni][0] = __expf(sc[ni][0] - mn0);
            sc[ni][1] = __expf(sc[ni][1] - mn0);
            sc[ni][2] = __expf(sc[ni][2] - mn1);
            sc[ni][3] = __expf(sc[ni][3] - mn1);
            s0 += sc[ni][0] + sc[ni][1];
            s1 += sc[ni][2] + sc[ni][3];
        }
        #pragma unroll
        for (int off = 1; off < 4; off <<= 1) {
            s0 += __shfl_xor_sync(0xffffffffu, s0, off);
            s1 += __shfl_xor_sync(0xffffffffu, s1, off);
        }
        l0 = l0*al0 + s0;
        l1 = l1*al1 + s1;
        m0r = mn0; m1r = mn1;

        #pragma unroll
        for (int ni = 0; ni < 8; ni++) {
            acc[ni][0] *= al0; acc[ni][1] *= al0;
            acc[ni][2] *= al1; acc[ni][3] *= al1;
            const int col = ni*8 + 2*tg;
            *(uint2*)&Ps[rloc0*PSTR + col] =
                make_uint2(f2tf32(sc[ni][0]), f2tf32(sc[ni][1]));
            *(uint2*)&Ps[(rloc0 + 8)*PSTR + col] =
                make_uint2(f2tf32(sc[ni][2]), f2tf32(sc[ni][3]));
        }
        __syncwarp();

        #pragma unroll
        for (int kk = 0; kk < 8; kk++) {
            const int kc = kk * 8;
            uint32_t a[4];
            const int pb = rloc0*PSTR + kc + tg;
            a[0] = Ps[pb];
            a[1] = Ps[pb + 8*PSTR];
            a[2] = Ps[pb + 4];
            a[3] = Ps[pb + 8*PSTR + 4];
            #pragma unroll
            for (int ni = 0; ni < 8; ni++) {
                uint32_t b[2];
                b[0] = Vs[(kc + tg    )*VSTR + ni*8 + g];
                b[1] = Vs[(kc + tg + 4)*VSTR + ni*8 + g];
                mma_tf32(acc[ni], a, b);
            }
        }
    }

    const float il0 = 1.f / l0;
    const float il1 = 1.f / l1;
    const int b_ = bh >> 4, nh = bh & 15;
    #pragma unroll
    for (int ni = 0; ni < 8; ni++) {
        const int col = nh*HDD + ni*8 + 2*tg;
        *(float2*)&AO[(size_t)(b_*SS + row0)*HH + col] =
            make_float2(acc[ni][0]*il0, acc[ni][1]*il0);
        *(float2*)&AO[(size_t)(b_*SS + row1)*HH + col] =
            make_float2(acc[ni][2]*il1, acc[ni][3]*il1);
    }
}

// ---------------- launcher ---------------------------------------------------
static const int FLASH_SMEM = (FQ*QSTR + FK*KSTR + FK*VSTR + FQ*PSTR) * 4;  // 105472

extern "C" void kernel_launch(void* const* d_in, const int* in_sizes, int n_in,
                              void* d_out, int out_size)
{
    (void)in_sizes; (void)n_in; (void)out_size;
    const float* hs = (const float*)d_in[0];
    const float* wq = (const float*)d_in[2];
    const float* wk = (const float*)d_in[3];
    const float* wv = (const float*)d_in[4];
    const float* wo = (const float*)d_in[5];
    const int*  pos = (const int*)d_in[6];
    float* out = (float*)d_out;

    float *Q, *K, *V, *AO;
    cudaGetSymbolAddress((void**)&Q,  g_Q);
    cudaGetSymbolAddress((void**)&K,  g_K);
    cudaGetSymbolAddress((void**)&V,  g_V);
    cudaGetSymbolAddress((void**)&AO, g_AO);

    static bool attr_done = false;
    if (!attr_done) {
        cudaFuncSetAttribute(gemm_v2<0>,
                             cudaFuncAttributeMaxDynamicSharedMemorySize, GEMM_SMEM);
        cudaFuncSetAttribute(gemm_v2<1>,
                             cudaFuncAttributeMaxDynamicSharedMemorySize, GEMM_SMEM);
        cudaFuncSetAttribute(flash_tc,
                             cudaFuncAttributeMaxDynamicSharedMemorySize, FLASH_SMEM);
        attr_done = true;
    }

    gemm_v2<0><<<dim3(HH/GTN, MM/GTM, 3), 256, GEMM_SMEM>>>(hs, wq, wk, wv, Q, K, V);

    dummy_kernel<<<1, 32>>>();

    rope_kernel<<<(BB*NHH*SS*(HDD/2)) / 256, 256>>>(Q, K, pos);

    flash_tc<<<dim3(SS/FQ, BB*NHH), 256, FLASH_SMEM>>>(Q, K, V, AO);

    gemm_v2<1><<<dim3(HH/GTN, MM/GTM, 1), 256, GEMM_SMEM>>>(AO, wo, wo, wo, out, out, out);
}

// round 7
// speedup vs baseline: 1.8892x; 1.5928x over previous
#include <cuda_runtime.h>
#include <cuda_fp16.h>
#include <cstdint>
#include <math.h>

#define BB 2
#define SS 2048
#define HH 1024
#define NHH 16
#define HDD 64
#define MM (BB*SS)   // 4096

// ---------------- scratch (allocation-free: device globals) ----------------
__device__ float    g_Q[BB*NHH*SS*HDD];
__device__ float    g_K[BB*NHH*SS*HDD];
__device__ float    g_V[BB*NHH*SS*HDD];
__device__ float    g_AO[MM*HH];
__device__ uint32_t g_Qh[BB*NHH*SS*(HDD/2)];      // fp16 pairs along d
__device__ uint32_t g_Kh[BB*NHH*SS*(HDD/2)];      // fp16 pairs along d
__device__ uint32_t g_Vh[BB*NHH*HDD*(SS/2)];      // [bh][d][s-pair]

// ---------------- helpers ----------------------------------------------------
__device__ __forceinline__ uint32_t fpack(float a, float b) {
    __half2 h = __floats2half2_rn(a, b);
    return *reinterpret_cast<uint32_t*>(&h);
}

__device__ __forceinline__ void mma_fp16(float c[4], const uint32_t a[4], const uint32_t b[2]) {
    asm volatile(
        "mma.sync.aligned.m16n8k16.row.col.f32.f16.f16.f32 "
        "{%0,%1,%2,%3}, {%4,%5,%6,%7}, {%8,%9}, {%0,%1,%2,%3};"
        : "+f"(c[0]), "+f"(c[1]), "+f"(c[2]), "+f"(c[3])
        : "r"(a[0]), "r"(a[1]), "r"(a[2]), "r"(a[3]),
          "r"(b[0]), "r"(b[1]));
}

__device__ __forceinline__ uint32_t smem_u32(const void* p) {
    uint32_t a;
    asm("{ .reg .u64 t; cvta.to.shared.u64 t, %1; cvt.u32.u64 %0, t; }" : "=r"(a) : "l"(p));
    return a;
}

#define CPA16(dst, src) \
    asm volatile("cp.async.cg.shared.global [%0], [%1], 16;" :: "r"(dst), "l"(src))
#define CPA_COMMIT() asm volatile("cp.async.commit_group;" ::: "memory")
#define CPA_WAIT0()  asm volatile("cp.async.wait_group 0;" ::: "memory")
#define CPA_WAIT1()  asm volatile("cp.async.wait_group 1;" ::: "memory")

// ---------------- GEMM v3: fp16 m16n8k16, 128x256 CTA, 64x64 warp tile ------
// Y[m,o] = sum_h A[m,h] * W[o,h].  K-chunk 16 = one k16 MMA step.
// Smem: pair-packed fp16, row stride 12 u32 (8 kp + 4 pad) -> conflict-free
// fragment LDS (bank = 12g + tg mod 32, all 32 distinct).
#define GTM 128
#define GTN 256
#define GKC 16
#define ASTR 12
#define GSTAGE ((GTM + GTN) * ASTR)                      // 4608 u32
static const int GEMM_SMEM = 2 * GSTAGE * (int)sizeof(uint32_t);  // 36864

template<int MODE>
__global__ void __launch_bounds__(256, 1) gemm_v3(const float* __restrict__ A,
                                                  const float* __restrict__ W0,
                                                  const float* __restrict__ W1,
                                                  const float* __restrict__ W2,
                                                  float* __restrict__ Y0,
                                                  float* __restrict__ Y1,
                                                  float* __restrict__ Y2)
{
    extern __shared__ uint32_t sm2[];
    const float* W = (blockIdx.z == 0) ? W0 : (blockIdx.z == 1) ? W1 : W2;
    float* Y       = (blockIdx.z == 0) ? Y0 : (blockIdx.z == 1) ? Y1 : Y2;

    const int tid  = threadIdx.x;
    const int w    = tid >> 5;
    const int lane = tid & 31;
    const int g    = lane >> 2;
    const int tg   = lane & 3;
    const int wm   = (w & 1) * 64;
    const int wn   = (w >> 1) * 64;
    const int m0   = blockIdx.y * GTM;
    const int n0   = blockIdx.x * GTN;

    float acc[4][8][4];
    #pragma unroll
    for (int mi = 0; mi < 4; mi++)
        #pragma unroll
        for (int ni = 0; ni < 8; ni++)
            #pragma unroll
            for (int r = 0; r < 4; r++) acc[mi][ni][r] = 0.f;

    float4 a_st[2], w_st[4];

    #define LDG_T(KO)                                                             \
        _Pragma("unroll")                                                         \
        for (int r = 0; r < 2; r++) {                                             \
            const int idx = r * 256 + tid;                                        \
            const int row = idx >> 2, j = idx & 3;                                \
            a_st[r] = *(const float4*)&A[(size_t)(m0 + row) * HH + (KO) + j * 4]; \
        }                                                                         \
        _Pragma("unroll")                                                         \
        for (int r = 0; r < 4; r++) {                                             \
            const int idx = r * 256 + tid;                                        \
            const int row = idx >> 2, j = idx & 3;                                \
            w_st[r] = *(const float4*)&W[(size_t)(n0 + row) * HH + (KO) + j * 4]; \
        }

    #define STS_T(S)                                                              \
        {                                                                         \
            uint32_t* dA = sm2 + (S) * GSTAGE;                                    \
            uint32_t* dW = dA + GTM * ASTR;                                       \
            _Pragma("unroll")                                                     \
            for (int r = 0; r < 2; r++) {                                         \
                const int idx = r * 256 + tid;                                    \
                const int row = idx >> 2, j = idx & 3;                            \
                uint2 v = make_uint2(fpack(a_st[r].x, a_st[r].y),                 \
                                     fpack(a_st[r].z, a_st[r].w));                \
                *(uint2*)&dA[row * ASTR + 2 * j] = v;                             \
            }                                                                     \
            _Pragma("unroll")                                                     \
            for (int r = 0; r < 4; r++) {                                         \
                const int idx = r * 256 + tid;                                    \
                const int row = idx >> 2, j = idx & 3;                            \
                uint2 v = make_uint2(fpack(w_st[r].x, w_st[r].y),                 \
                                     fpack(w_st[r].z, w_st[r].w));                \
                *(uint2*)&dW[row * ASTR + 2 * j] = v;                             \
            }                                                                     \
        }

    LDG_T(0);
    STS_T(0);
    __syncthreads();

    const int NIT = HH / GKC;            // 64
    #pragma unroll 1
    for (int it = 0; it < NIT; it++) {
        if (it + 1 < NIT) LDG_T((it + 1) * GKC);

        const uint32_t* cA = sm2 + (it & 1) * GSTAGE;
        const uint32_t* cW = cA + GTM * ASTR;

        uint32_t a[4][4], b[8][2];
        #pragma unroll
        for (int mi = 0; mi < 4; mi++) {
            const int r0 = (wm + 16 * mi + g) * ASTR;
            const int r8 = r0 + 8 * ASTR;
            a[mi][0] = cA[r0 + tg];
            a[mi][1] = cA[r8 + tg];
            a[mi][2] = cA[r0 + tg + 4];
            a[mi][3] = cA[r8 + tg + 4];
        }
        #pragma unroll
        for (int ni = 0; ni < 8; ni++) {
            const int rb = (wn + 8 * ni + g) * ASTR;
            b[ni][0] = cW[rb + tg];
            b[ni][1] = cW[rb + tg + 4];
        }
        #pragma unroll
        for (int mi = 0; mi < 4; mi++)
            #pragma unroll
            for (int ni = 0; ni < 8; ni++)
                mma_fp16(acc[mi][ni], a[mi], b[ni]);

        if (it + 1 < NIT) STS_T((it + 1) & 1);
        __syncthreads();
    }

    #pragma unroll
    for (int mi = 0; mi < 4; mi++) {
        #pragma unroll
        for (int ni = 0; ni < 8; ni++) {
            const int row = m0 + wm + 16 * mi + g;
            const int col = n0 + wn + 8 * ni + 2 * tg;
            float2 v0 = make_float2(acc[mi][ni][0], acc[mi][ni][1]);
            float2 v1 = make_float2(acc[mi][ni][2], acc[mi][ni][3]);
            if (MODE == 0) {
                const int nh = col >> 6, hd = col & 63;
                {
                    const int b_ = row >> 11, s = row & (SS - 1);
                    *(float2*)&Y[(((size_t)(b_ * NHH + nh) * SS + s) * HDD) + hd] = v0;
                }
                {
                    const int row8 = row + 8;
                    const int b_ = row8 >> 11, s = row8 & (SS - 1);
                    *(float2*)&Y[(((size_t)(b_ * NHH + nh) * SS + s) * HDD) + hd] = v1;
                }
            } else {
                *(float2*)&Y[(size_t)row * HH + col] = v0;
                *(float2*)&Y[(size_t)(row + 8) * HH + col] = v1;
            }
        }
    }
    #undef LDG_T
    #undef STS_T
}

// ---------------- prep: RoPE Q,K -> fp16 pairs; Q pre-scaled by 0.125 -------
// block 256 = 32 rows x 8 j-threads; grid (SS/32, BB*NHH)
__global__ void __launch_bounds__(256) prep_qk(const float* __restrict__ Q,
                                               const float* __restrict__ K,
                                               const int* __restrict__ pos_ids,
                                               uint32_t* __restrict__ Qh,
                                               uint32_t* __restrict__ Kh)
{
    const int tid = threadIdx.x;
    const int r   = tid >> 3;
    const int j   = tid & 7;
    const int s   = blockIdx.x * 32 + r;
    const int bh  = blockIdx.y;
    const int b   = bh >> 4;

    int p = pos_ids[b * SS + s];
    p = min(max(p, 0), SS - 1);

    const size_t base = ((size_t)bh * SS + s) * HDD;
    const float4 q0 = *(const float4*)&Q[base + 4 * j];
    const float4 q1 = *(const float4*)&Q[base + 4 * j + 32];
    const float4 k0 = *(const float4*)&K[base + 4 * j];
    const float4 k1 = *(const float4*)&K[base + 4 * j + 32];

    float ql[4], qh[4], kl[4], kh[4];
    const float x0[4] = {q0.x, q0.y, q0.z, q0.w};
    const float x1[4] = {q1.x, q1.y, q1.z, q1.w};
    const float y0[4] = {k0.x, k0.y, k0.z, k0.w};
    const float y1[4] = {k1.x, k1.y, k1.z, k1.w};
    #pragma unroll
    for (int e = 0; e < 4; e++) {
        const int i = 4 * j + e;
        const float inv = expf(-(float)i * (logf(10000.0f) / 32.0f));
        float sn, cs;
        sincosf((float)p * inv, &sn, &cs);
        ql[e] = (x0[e] * cs - x1[e] * sn) * 0.125f;
        qh[e] = (x1[e] * cs + x0[e] * sn) * 0.125f;
        kl[e] = y0[e] * cs - y1[e] * sn;
        kh[e] = y1[e] * cs + y0[e] * sn;
    }

    const size_t ob = ((size_t)bh * SS + s) * 32;
    *(uint2*)&Qh[ob + 2 * j]      = make_uint2(fpack(ql[0], ql[1]), fpack(ql[2], ql[3]));
    *(uint2*)&Qh[ob + 16 + 2 * j] = make_uint2(fpack(qh[0], qh[1]), fpack(qh[2], qh[3]));
    *(uint2*)&Kh[ob + 2 * j]      = make_uint2(fpack(kl[0], kl[1]), fpack(kl[2], kl[3]));
    *(uint2*)&Kh[ob + 16 + 2 * j] = make_uint2(fpack(kh[0], kh[1]), fpack(kh[2], kh[3]));
}

// ---------------- prep: V -> fp16 transposed s-pairs [bh][d][sp] -------------
// grid (SS/64, BB*NHH), block 256
__global__ void __launch_bounds__(256) prep_v(const float* __restrict__ V,
                                              uint32_t* __restrict__ Vh)
{
    __shared__ float vs[64 * 68];
    const int tid = threadIdx.x;
    const int bh  = blockIdx.y;
    const int st  = blockIdx.x * 64;
    const size_t base = ((size_t)bh * SS + st) * HDD;

    #pragma unroll
    for (int i = 0; i < 4; i++) {
        const int idx4 = tid + i * 256;          // 1024 float4s
        const int srow = idx4 >> 4, d4 = idx4 & 15;
        float4 v = *(const float4*)&V[base + (size_t)srow * HDD + d4 * 4];
        *(float4*)&vs[srow * 68 + d4 * 4] = v;
    }
    __syncthreads();

    #pragma unroll
    for (int i = 0; i < 2; i++) {
        const int u4 = tid + i * 256;            // 512 uint4s
        const int d = u4 & 63, q = (u4 >> 6) & 7;
        uint32_t o[4];
        #pragma unroll
        for (int k = 0; k < 4; k++) {
            const int sp = 4 * q + k;
            o[k] = fpack(vs[(2 * sp) * 68 + d], vs[(2 * sp + 1) * 68 + d]);
        }
        *(uint4*)&Vh[((size_t)bh * HDD + d) * (SS / 2) + (st >> 1) + 4 * q] =
            make_uint4(o[0], o[1], o[2], o[3]);
    }
}

// ---------------- flash attention: fp16 MMA, P in registers, cp.async -------
// Q tile 128 x K tile 64; 8 warps x 16 rows. Double-buffered K/V via cp.async.
#define FQ 128
#define FK 64
#define HSTR 36
#define SQ_OFF 0
#define SK_OFF (FQ * HSTR)              // 4608
#define STG_SZ (FK * HSTR * 2)          // 4608 (K then V)
static const int FLASH_SMEM = (FQ * HSTR + 2 * STG_SZ) * (int)sizeof(uint32_t);  // 55296

__global__ void __launch_bounds__(256, 2) flash_fp16(const uint32_t* __restrict__ Qh,
                                                     const uint32_t* __restrict__ Kh,
                                                     const uint32_t* __restrict__ Vh,
                                                     float* __restrict__ AO)
{
    extern __shared__ uint32_t fsm[];
    const uint32_t sb = smem_u32(fsm);

    const int tid  = threadIdx.x;
    const int w    = tid >> 5;
    const int lane = tid & 31;
    const int g    = lane >> 2;
    const int tg   = lane & 3;
    const int bh   = blockIdx.y;
    const int qt   = (int)(gridDim.x - 1) - (int)blockIdx.x;  // heavy first
    const int q0   = qt * FQ;

    const uint32_t* qsrc = Qh + ((size_t)bh * SS + q0) * 32;
    const uint32_t* ksrc = Kh + (size_t)bh * SS * 32;
    const uint32_t* vsrc = Vh + (size_t)bh * HDD * (SS / 2);

    const int nt = 2 * qt + 2;

    #define ISSUE_KV(KT, STG)                                                     \
        {                                                                         \
            _Pragma("unroll")                                                     \
            for (int i = 0; i < 2; i++) {                                         \
                const int c = tid + i * 256;                                      \
                const int row = c >> 3, j = c & 7;                                \
                CPA16(sb + (SK_OFF + (STG) * STG_SZ + row * HSTR + j * 4) * 4,    \
                      ksrc + ((size_t)(KT) * FK + row) * 32 + j * 4);             \
            }                                                                     \
            _Pragma("unroll")                                                     \
            for (int i = 0; i < 2; i++) {                                         \
                const int c = tid + i * 256;                                      \
                const int d = c >> 3, j = c & 7;                                  \
                CPA16(sb + (SK_OFF + (STG) * STG_SZ + FK * HSTR + d * HSTR + j * 4) * 4, \
                      vsrc + (size_t)d * (SS / 2) + (KT) * 32 + j * 4);           \
            }                                                                     \
        }

    // prologue: Q + tile0 -> group0; tile1 -> group1
    #pragma unroll
    for (int i = 0; i < 4; i++) {
        const int c = tid + i * 256;             // 1024 chunks
        const int row = c >> 3, j = c & 7;
        CPA16(sb + (SQ_OFF + row * HSTR + j * 4) * 4, qsrc + (size_t)row * 32 + j * 4);
    }
    ISSUE_KV(0, 0);
    CPA_COMMIT();
    if (nt > 1) { ISSUE_KV(1, 1); CPA_COMMIT(); }

    float m0r = -1e30f, m1r = -1e30f, l0 = 0.f, l1 = 0.f;
    float acc[8][4];
    #pragma unroll
    for (int ni = 0; ni < 8; ni++)
        #pragma unroll
        for (int r = 0; r < 4; r++) acc[ni][r] = 0.f;

    const int rloc0 = w * 16 + g;
    const int row0  = q0 + rloc0;
    const int row1  = row0 + 8;

    const uint32_t* Qs = fsm;

    #pragma unroll 1
    for (int kt = 0; kt < nt; kt++) {
        if (kt + 1 < nt) { CPA_WAIT1(); } else { CPA_WAIT0(); }
        __syncthreads();

        const uint32_t* Ks = fsm + SK_OFF + (kt & 1) * STG_SZ;
        const uint32_t* Vs = Ks + FK * HSTR;
        const int k0 = kt * FK;

        // GEMM1: scores = Q . K^T  (fp16 k16)
        float sc[8][4];
        #pragma unroll
        for (int ni = 0; ni < 8; ni++)
            #pragma unroll
            for (int r = 0; r < 4; r++) sc[ni][r] = 0.f;

        #pragma unroll
        for (int kk = 0; kk < 4; kk++) {
            uint32_t a[4];
            const int r0b = rloc0 * HSTR + 8 * kk + tg;
            a[0] = Qs[r0b];
            a[1] = Qs[r0b + 8 * HSTR];
            a[2] = Qs[r0b + 4];
            a[3] = Qs[r0b + 8 * HSTR + 4];
            #pragma unroll
            for (int ni = 0; ni < 8; ni++) {
                uint32_t b[2];
                const int nb = (ni * 8 + g) * HSTR + 8 * kk + tg;
                b[0] = Ks[nb];
                b[1] = Ks[nb + 4];
                mma_fp16(sc[ni], a, b);
            }
        }

        // causal mask on diagonal band
        if (kt >= 2 * qt) {
            #pragma unroll
            for (int ni = 0; ni < 8; ni++) {
                const int c = k0 + ni * 8 + 2 * tg;
                if (c     > row0) sc[ni][0] = -1e30f;
                if (c + 1 > row0) sc[ni][1] = -1e30f;
                if (c     > row1) sc[ni][2] = -1e30f;
                if (c + 1 > row1) sc[ni][3] = -1e30f;
            }
        }

        // online softmax (quad reduction)
        float mx0 = -1e30f, mx1 = -1e30f;
        #pragma unroll
        for (int ni = 0; ni < 8; ni++) {
            mx0 = fmaxf(mx0, fmaxf(sc[ni][0], sc[ni][1]));
            mx1 = fmaxf(mx1, fmaxf(sc[ni][2], sc[ni][3]));
        }
        #pragma unroll
        for (int off = 1; off < 4; off <<= 1) {
            mx0 = fmaxf(mx0, __shfl_xor_sync(0xffffffffu, mx0, off));
            mx1 = fmaxf(mx1, __shfl_xor_sync(0xffffffffu, mx1, off));
        }
        const float mn0 = fmaxf(m0r, mx0);
        const float mn1 = fmaxf(m1r, mx1);
        const float al0 = __expf(m0r - mn0);
        const float al1 = __expf(m1r - mn1);

        float s0 = 0.f, s1 = 0.f;
        #pragma unroll
        for (int ni = 0; ni < 8; ni++) {
            sc[ni][0] = __expf(sc[ni][0] - mn0);
            sc[ni][1] = __expf(sc[ni][1] - mn0);
            sc[ni][2] = __expf(sc[ni][2] - mn1);
            sc[ni][3] = __expf(sc[ni][3] - mn1);
            s0 += sc[ni][0] + sc[ni][1];
            s1 += sc[ni][2] + sc[ni][3];
        }
        #pragma unroll
        for (int off = 1; off < 4; off <<= 1) {
            s0 += __shfl_xor_sync(0xffffffffu, s0, off);
            s1 += __shfl_xor_sync(0xffffffffu, s1, off);
        }
        l0 = l0 * al0 + s0;
        l1 = l1 * al1 + s1;
        m0r = mn0; m1r = mn1;

        // P -> fp16 registers (C fragment == A fragment layout)
        uint32_t ph[8][2];
        #pragma unroll
        for (int ni = 0; ni < 8; ni++) {
            acc[ni][0] *= al0; acc[ni][1] *= al0;
            acc[ni][2] *= al1; acc[ni][3] *= al1;
            ph[ni][0] = fpack(sc[ni][0], sc[ni][1]);
            ph[ni][1] = fpack(sc[ni][2], sc[ni][3]);
        }

        // GEMM2: acc += P . V  (fp16 k16, A from registers)
        #pragma unroll
        for (int kk = 0; kk < 4; kk++) {
            uint32_t a[4];
            a[0] = ph[2 * kk][0];
            a[1] = ph[2 * kk][1];
            a[2] = ph[2 * kk + 1][0];
            a[3] = ph[2 * kk + 1][1];
            #pragma unroll
            for (int ni = 0; ni < 8; ni++) {
                uint32_t b[2];
                const int nb = (ni * 8 + g) * HSTR + 8 * kk + tg;
                b[0] = Vs[nb];
                b[1] = Vs[nb + 4];
                mma_fp16(acc[ni], a, b);
            }
        }

        __syncthreads();
        if (kt + 2 < nt) { ISSUE_KV(kt + 2, kt & 1); CPA_COMMIT(); }
    }

    // epilogue
    const float il0 = 1.f / l0;
    const float il1 = 1.f / l1;
    const int b_ = bh >> 4, nh = bh & 15;
    #pragma unroll
    for (int ni = 0; ni < 8; ni++) {
        const int col = nh * HDD + ni * 8 + 2 * tg;
        *(float2*)&AO[(size_t)(b_ * SS + row0) * HH + col] =
            make_float2(acc[ni][0] * il0, acc[ni][1] * il0);
        *(float2*)&AO[(size_t)(b_ * SS + row1) * HH + col] =
            make_float2(acc[ni][2] * il1, acc[ni][3] * il1);
    }
    #undef ISSUE_KV
}

// ---------------- launcher ---------------------------------------------------
extern "C" void kernel_launch(void* const* d_in, const int* in_sizes, int n_in,
                              void* d_out, int out_size)
{
    (void)in_sizes; (void)n_in; (void)out_size;
    const float* hs = (const float*)d_in[0];
    const float* wq = (const float*)d_in[2];
    const float* wk = (const float*)d_in[3];
    const float* wv = (const float*)d_in[4];
    const float* wo = (const float*)d_in[5];
    const int*  pos = (const int*)d_in[6];
    float* out = (float*)d_out;

    float *Q, *K, *V, *AO;
    uint32_t *Qh, *Kh, *Vh;
    cudaGetSymbolAddress((void**)&Q,  g_Q);
    cudaGetSymbolAddress((void**)&K,  g_K);
    cudaGetSymbolAddress((void**)&V,  g_V);
    cudaGetSymbolAddress((void**)&AO, g_AO);
    cudaGetSymbolAddress((void**)&Qh, g_Qh);
    cudaGetSymbolAddress((void**)&Kh, g_Kh);
    cudaGetSymbolAddress((void**)&Vh, g_Vh);

    static bool attr_done = false;
    if (!attr_done) {
        cudaFuncSetAttribute(gemm_v3<0>,
                             cudaFuncAttributeMaxDynamicSharedMemorySize, GEMM_SMEM);
        cudaFuncSetAttribute(gemm_v3<1>,
                             cudaFuncAttributeMaxDynamicSharedMemorySize, GEMM_SMEM);
        cudaFuncSetAttribute(flash_fp16,
                             cudaFuncAttributeMaxDynamicSharedMemorySize, FLASH_SMEM);
        attr_done = true;
    }

    gemm_v3<0><<<dim3(HH/GTN, MM/GTM, 3), 256, GEMM_SMEM>>>(hs, wq, wk, wv, Q, K, V);

    prep_qk<<<dim3(SS/32, BB*NHH), 256>>>(Q, K, pos, Qh, Kh);
    prep_v<<<dim3(SS/64, BB*NHH), 256>>>(V, Vh);

    flash_fp16<<<dim3(SS/FQ, BB*NHH), 256, FLASH_SMEM>>>(Qh, Kh, Vh, AO);

    gemm_v3<1><<<dim3(HH/GTN, MM/GTM, 1), 256, GEMM_SMEM>>>(AO, wo, wo, wo, out, out, out);
}

// round 8
// speedup vs baseline: 2.3560x; 1.2471x over previous
#include <cuda_runtime.h>
#include <cuda_fp16.h>
#include <cstdint>
#include <math.h>

#define BB 2
#define SS 2048
#define HH 1024
#define NHH 16
#define HDD 64
#define MM (BB*SS)   // 4096
#define HP (HH/2)    // 512 u32 per packed row

// ---------------- scratch (allocation-free: device globals) ----------------
__device__ float    g_Q[BB*NHH*SS*HDD];
__device__ float    g_K[BB*NHH*SS*HDD];
__device__ float    g_V[BB*NHH*SS*HDD];
__device__ uint32_t g_Hh [MM*HP];                 // hs fp16 packed
__device__ uint32_t g_Wqh[HH*HP];
__device__ uint32_t g_Wkh[HH*HP];
__device__ uint32_t g_Wvh[HH*HP];
__device__ uint32_t g_Woh[HH*HP];
__device__ uint32_t g_AOh[MM*HP];                 // attention out fp16 packed
__device__ uint32_t g_Qh[BB*NHH*SS*(HDD/2)];
__device__ uint32_t g_Kh[BB*NHH*SS*(HDD/2)];
__device__ uint32_t g_Vh[BB*NHH*HDD*(SS/2)];

// ---------------- helpers ----------------------------------------------------
__device__ __forceinline__ uint32_t fpack(float a, float b) {
    __half2 h = __floats2half2_rn(a, b);
    return *reinterpret_cast<uint32_t*>(&h);
}

__device__ __forceinline__ void mma_fp16(float c[4], const uint32_t a[4], const uint32_t b[2]) {
    asm volatile(
        "mma.sync.aligned.m16n8k16.row.col.f32.f16.f16.f32 "
        "{%0,%1,%2,%3}, {%4,%5,%6,%7}, {%8,%9}, {%0,%1,%2,%3};"
        : "+f"(c[0]), "+f"(c[1]), "+f"(c[2]), "+f"(c[3])
        : "r"(a[0]), "r"(a[1]), "r"(a[2]), "r"(a[3]),
          "r"(b[0]), "r"(b[1]));
}

__device__ __forceinline__ uint32_t smem_u32(const void* p) {
    uint32_t a;
    asm("{ .reg .u64 t; cvta.to.shared.u64 t, %1; cvt.u32.u64 %0, t; }" : "=r"(a) : "l"(p));
    return a;
}

#define CPA16(dst, src) \
    asm volatile("cp.async.cg.shared.global [%0], [%1], 16;" :: "r"(dst), "l"(src))
#define CPA_COMMIT() asm volatile("cp.async.commit_group;" ::: "memory")
#define CPA_WAIT0()  asm volatile("cp.async.wait_group 0;" ::: "memory")
#define CPA_WAIT1()  asm volatile("cp.async.wait_group 1;" ::: "memory")

// ---------------- fp32 -> fp16 pack pre-pass ---------------------------------
__global__ void __launch_bounds__(256) pack_fp16(const float* __restrict__ src,
                                                 uint32_t* __restrict__ dst, int n2)
{
    int i = blockIdx.x * blockDim.x + threadIdx.x;
    const int stride = gridDim.x * blockDim.x;
    for (; i < n2; i += stride) {
        float2 v = ((const float2*)src)[i];
        dst[i] = fpack(v.x, v.y);
    }
}

// ---------------- GEMM v4: pure-fp16 streams, cp.async 3-stage --------------
// Y[m,o] = sum_h A[m,h] * W[o,h]; A,B are fp16 pair-packed [row][HP].
// CTA 128x256, warp tile 64x64, K-chunk 32 (16 u32), NIT=32.
// Stage row stride 20 u32 (16 data + 4 pad): fragment LDS conflict-free.
#define GTM 128
#define GTN 256
#define GSTR 20
#define GSTAGE ((GTM + GTN) * GSTR)     // 7680 u32
static const int GEMM_SMEM = 3 * GSTAGE * (int)sizeof(uint32_t);  // 92160

template<int MODE>
__global__ void __launch_bounds__(256, 1) gemm_v4(const uint32_t* __restrict__ A,
                                                  const uint32_t* __restrict__ B0,
                                                  const uint32_t* __restrict__ B1,
                                                  const uint32_t* __restrict__ B2,
                                                  float* __restrict__ Y0,
                                                  float* __restrict__ Y1,
                                                  float* __restrict__ Y2)
{
    extern __shared__ uint32_t sm4[];
    const uint32_t* Bp = (blockIdx.z == 0) ? B0 : (blockIdx.z == 1) ? B1 : B2;
    float* Y           = (blockIdx.z == 0) ? Y0 : (blockIdx.z == 1) ? Y1 : Y2;

    const int tid  = threadIdx.x;
    const int w    = tid >> 5;
    const int lane = tid & 31;
    const int g    = lane >> 2;
    const int tg   = lane & 3;
    const int wm   = (w & 1) * 64;
    const int wn   = (w >> 1) * 64;
    const int m0   = blockIdx.y * GTM;
    const int n0   = blockIdx.x * GTN;
    const uint32_t sb = smem_u32(sm4);

    // 1536 16B-chunks per stage; 6 per thread. row = c>>2 (0..383), j = c&3.
    #define ISSUE_G(IT, STG)                                                      \
        _Pragma("unroll")                                                         \
        for (int i = 0; i < 6; i++) {                                             \
            const int c = tid + i * 256;                                          \
            const int row = c >> 2, j = c & 3;                                    \
            const uint32_t* src = (row < GTM)                                     \
                ? A  + (size_t)(m0 + row)       * HP + (IT) * 16 + j * 4          \
                : Bp + (size_t)(n0 + row - GTM) * HP + (IT) * 16 + j * 4;         \
            CPA16(sb + ((STG) * GSTAGE + row * GSTR + j * 4) * 4, src);           \
        }

    ISSUE_G(0, 0); CPA_COMMIT();
    ISSUE_G(1, 1); CPA_COMMIT();

    float acc[4][8][4];
    #pragma unroll
    for (int mi = 0; mi < 4; mi++)
        #pragma unroll
        for (int ni = 0; ni < 8; ni++)
            #pragma unroll
            for (int r = 0; r < 4; r++) acc[mi][ni][r] = 0.f;

    const int NIT = HP / 16;             // 32
    #pragma unroll 1
    for (int it = 0; it < NIT; it++) {
        if (it < NIT - 1) { CPA_WAIT1(); } else { CPA_WAIT0(); }
        __syncthreads();
        if (it + 2 < NIT) {
            const int stg = (it + 2) % 3;
            ISSUE_G(it + 2, stg);
            CPA_COMMIT();
        }

        const uint32_t* cS = sm4 + (it % 3) * GSTAGE;
        const uint32_t* cB = cS + GTM * GSTR;

        #pragma unroll
        for (int kk = 0; kk < 2; kk++) {
            const int kc = kk * 8;
            uint32_t a[4][4], b[8][2];
            #pragma unroll
            for (int mi = 0; mi < 4; mi++) {
                const int r0 = (wm + 16 * mi + g) * GSTR + kc;
                const int r8 = r0 + 8 * GSTR;
                a[mi][0] = cS[r0 + tg];
                a[mi][1] = cS[r8 + tg];
                a[mi][2] = cS[r0 + tg + 4];
                a[mi][3] = cS[r8 + tg + 4];
            }
            #pragma unroll
            for (int ni = 0; ni < 8; ni++) {
                const int rb = (wn + 8 * ni + g) * GSTR + kc;
                b[ni][0] = cB[rb + tg];
                b[ni][1] = cB[rb + tg + 4];
            }
            #pragma unroll
            for (int mi = 0; mi < 4; mi++)
                #pragma unroll
                for (int ni = 0; ni < 8; ni++)
                    mma_fp16(acc[mi][ni], a[mi], b[ni]);
        }
        __syncthreads();
    }

    #pragma unroll
    for (int mi = 0; mi < 4; mi++) {
        #pragma unroll
        for (int ni = 0; ni < 8; ni++) {
            const int row = m0 + wm + 16 * mi + g;
            const int col = n0 + wn + 8 * ni + 2 * tg;
            float2 v0 = make_float2(acc[mi][ni][0], acc[mi][ni][1]);
            float2 v1 = make_float2(acc[mi][ni][2], acc[mi][ni][3]);
            if (MODE == 0) {
                const int nh = col >> 6, hd = col & 63;
                {
                    const int b_ = row >> 11, s = row & (SS - 1);
                    *(float2*)&Y[(((size_t)(b_ * NHH + nh) * SS + s) * HDD) + hd] = v0;
                }
                {
                    const int row8 = row + 8;
                    const int b_ = row8 >> 11, s = row8 & (SS - 1);
                    *(float2*)&Y[(((size_t)(b_ * NHH + nh) * SS + s) * HDD) + hd] = v1;
                }
            } else {
                *(float2*)&Y[(size_t)row * HH + col] = v0;
                *(float2*)&Y[(size_t)(row + 8) * HH + col] = v1;
            }
        }
    }
    #undef ISSUE_G
}

// ---------------- prep: RoPE Q,K -> fp16 pairs; Q pre-scaled by 0.125 -------
__global__ void __launch_bounds__(256) prep_qk(const float* __restrict__ Q,
                                               const float* __restrict__ K,
                                               const int* __restrict__ pos_ids,
                                               uint32_t* __restrict__ Qh,
                                               uint32_t* __restrict__ Kh)
{
    const int tid = threadIdx.x;
    const int r   = tid >> 3;
    const int j   = tid & 7;
    const int s   = blockIdx.x * 32 + r;
    const int bh  = blockIdx.y;
    const int b   = bh >> 4;

    int p = pos_ids[b * SS + s];
    p = min(max(p, 0), SS - 1);

    const size_t base = ((size_t)bh * SS + s) * HDD;
    const float4 q0 = *(const float4*)&Q[base + 4 * j];
    const float4 q1 = *(const float4*)&Q[base + 4 * j + 32];
    const float4 k0 = *(const float4*)&K[base + 4 * j];
    const float4 k1 = *(const float4*)&K[base + 4 * j + 32];

    float ql[4], qh[4], kl[4], kh[4];
    const float x0[4] = {q0.x, q0.y, q0.z, q0.w};
    const float x1[4] = {q1.x, q1.y, q1.z, q1.w};
    const float y0[4] = {k0.x, k0.y, k0.z, k0.w};
    const float y1[4] = {k1.x, k1.y, k1.z, k1.w};
    #pragma unroll
    for (int e = 0; e < 4; e++) {
        const int i = 4 * j + e;
        const float inv = expf(-(float)i * (logf(10000.0f) / 32.0f));
        float sn, cs;
        sincosf((float)p * inv, &sn, &cs);
        ql[e] = (x0[e] * cs - x1[e] * sn) * 0.125f;
        qh[e] = (x1[e] * cs + x0[e] * sn) * 0.125f;
        kl[e] = y0[e] * cs - y1[e] * sn;
        kh[e] = y1[e] * cs + y0[e] * sn;
    }

    const size_t ob = ((size_t)bh * SS + s) * 32;
    *(uint2*)&Qh[ob + 2 * j]      = make_uint2(fpack(ql[0], ql[1]), fpack(ql[2], ql[3]));
    *(uint2*)&Qh[ob + 16 + 2 * j] = make_uint2(fpack(qh[0], qh[1]), fpack(qh[2], qh[3]));
    *(uint2*)&Kh[ob + 2 * j]      = make_uint2(fpack(kl[0], kl[1]), fpack(kl[2], kl[3]));
    *(uint2*)&Kh[ob + 16 + 2 * j] = make_uint2(fpack(kh[0], kh[1]), fpack(kh[2], kh[3]));
}

// ---------------- prep: V -> fp16 transposed s-pairs [bh][d][sp] -------------
__global__ void __launch_bounds__(256) prep_v(const float* __restrict__ V,
                                              uint32_t* __restrict__ Vh)
{
    __shared__ float vs[64 * 68];
    const int tid = threadIdx.x;
    const int bh  = blockIdx.y;
    const int st  = blockIdx.x * 64;
    const size_t base = ((size_t)bh * SS + st) * HDD;

    #pragma unroll
    for (int i = 0; i < 4; i++) {
        const int idx4 = tid + i * 256;
        const int srow = idx4 >> 4, d4 = idx4 & 15;
        float4 v = *(const float4*)&V[base + (size_t)srow * HDD + d4 * 4];
        *(float4*)&vs[srow * 68 + d4 * 4] = v;
    }
    __syncthreads();

    #pragma unroll
    for (int i = 0; i < 2; i++) {
        const int u4 = tid + i * 256;
        const int d = u4 & 63, q = (u4 >> 6) & 7;
        uint32_t o[4];
        #pragma unroll
        for (int k = 0; k < 4; k++) {
            const int sp = 4 * q + k;
            o[k] = fpack(vs[(2 * sp) * 68 + d], vs[(2 * sp + 1) * 68 + d]);
        }
        *(uint4*)&Vh[((size_t)bh * HDD + d) * (SS / 2) + (st >> 1) + 4 * q] =
            make_uint4(o[0], o[1], o[2], o[3]);
    }
}

// ---------------- flash attention: fp16 MMA, P in registers, cp.async -------
#define FQ 128
#define FK 64
#define HSTR 36
#define SQ_OFF 0
#define SK_OFF (FQ * HSTR)
#define STG_SZ (FK * HSTR * 2)
static const int FLASH_SMEM = (FQ * HSTR + 2 * STG_SZ) * (int)sizeof(uint32_t);  // 55296

__global__ void __launch_bounds__(256, 2) flash_fp16(const uint32_t* __restrict__ Qh,
                                                     const uint32_t* __restrict__ Kh,
                                                     const uint32_t* __restrict__ Vh,
                                                     uint32_t* __restrict__ AOh)
{
    extern __shared__ uint32_t fsm[];
    const uint32_t sb = smem_u32(fsm);

    const int tid  = threadIdx.x;
    const int w    = tid >> 5;
    const int lane = tid & 31;
    const int g    = lane >> 2;
    const int tg   = lane & 3;
    const int bh   = blockIdx.y;
    const int qt   = (int)(gridDim.x - 1) - (int)blockIdx.x;
    const int q0   = qt * FQ;

    const uint32_t* qsrc = Qh + ((size_t)bh * SS + q0) * 32;
    const uint32_t* ksrc = Kh + (size_t)bh * SS * 32;
    const uint32_t* vsrc = Vh + (size_t)bh * HDD * (SS / 2);

    const int nt = 2 * qt + 2;

    #define ISSUE_KV(KT, STG)                                                     \
        {                                                                         \
            _Pragma("unroll")                                                     \
            for (int i = 0; i < 2; i++) {                                         \
                const int c = tid + i * 256;                                      \
                const int row = c >> 3, j = c & 7;                                \
                CPA16(sb + (SK_OFF + (STG) * STG_SZ + row * HSTR + j * 4) * 4,    \
                      ksrc + ((size_t)(KT) * FK + row) * 32 + j * 4);             \
            }                                                                     \
            _Pragma("unroll")                                                     \
            for (int i = 0; i < 2; i++) {                                         \
                const int c = tid + i * 256;                                      \
                const int d = c >> 3, j = c & 7;                                  \
                CPA16(sb + (SK_OFF + (STG) * STG_SZ + FK * HSTR + d * HSTR + j * 4) * 4, \
                      vsrc + (size_t)d * (SS / 2) + (KT) * 32 + j * 4);           \
            }                                                                     \
        }

    #pragma unroll
    for (int i = 0; i < 4; i++) {
        const int c = tid + i * 256;
        const int row = c >> 3, j = c & 7;
        CPA16(sb + (SQ_OFF + row * HSTR + j * 4) * 4, qsrc + (size_t)row * 32 + j * 4);
    }
    ISSUE_KV(0, 0);
    CPA_COMMIT();
    if (nt > 1) { ISSUE_KV(1, 1); CPA_COMMIT(); }

    float m0r = -1e30f, m1r = -1e30f, l0 = 0.f, l1 = 0.f;
    float acc[8][4];
    #pragma unroll
    for (int ni = 0; ni < 8; ni++)
        #pragma unroll
        for (int r = 0; r < 4; r++) acc[ni][r] = 0.f;

    const int rloc0 = w * 16 + g;
    const int row0  = q0 + rloc0;
    const int row1  = row0 + 8;

    const uint32_t* Qs = fsm;

    #pragma unroll 1
    for (int kt = 0; kt < nt; kt++) {
        if (kt + 1 < nt) { CPA_WAIT1(); } else { CPA_WAIT0(); }
        __syncthreads();

        const uint32_t* Ks = fsm + SK_OFF + (kt & 1) * STG_SZ;
        const uint32_t* Vs = Ks + FK * HSTR;
        const int k0 = kt * FK;

        float sc[8][4];
        #pragma unroll
        for (int ni = 0; ni < 8; ni++)
            #pragma unroll
            for (int r = 0; r < 4; r++) sc[ni][r] = 0.f;

        #pragma unroll
        for (int kk = 0; kk < 4; kk++) {
            uint32_t a[4];
            const int r0b = rloc0 * HSTR + 8 * kk + tg;
            a[0] = Qs[r0b];
            a[1] = Qs[r0b + 8 * HSTR];
            a[2] = Qs[r0b + 4];
            a[3] = Qs[r0b + 8 * HSTR + 4];
            #pragma unroll
            for (int ni = 0; ni < 8; ni++) {
                uint32_t b[2];
                const int nb = (ni * 8 + g) * HSTR + 8 * kk + tg;
                b[0] = Ks[nb];
                b[1] = Ks[nb + 4];
                mma_fp16(sc[ni], a, b);
            }
        }

        if (kt >= 2 * qt) {
            #pragma unroll
            for (int ni = 0; ni < 8; ni++) {
                const int c = k0 + ni * 8 + 2 * tg;
                if (c     > row0) sc[ni][0] = -1e30f;
                if (c + 1 > row0) sc[ni][1] = -1e30f;
                if (c     > row1) sc[ni][2] = -1e30f;
                if (c + 1 > row1) sc[ni][3] = -1e30f;
            }
        }

        float mx0 = -1e30f, mx1 = -1e30f;
        #pragma unroll
        for (int ni = 0; ni < 8; ni++) {
            mx0 = fmaxf(mx0, fmaxf(sc[ni][0], sc[ni][1]));
            mx1 = fmaxf(mx1, fmaxf(sc[ni][2], sc[ni][3]));
        }
        #pragma unroll
        for (int off = 1; off < 4; off <<= 1) {
            mx0 = fmaxf(mx0, __shfl_xor_sync(0xffffffffu, mx0, off));
            mx1 = fmaxf(mx1, __shfl_xor_sync(0xffffffffu, mx1, off));
        }
        const float mn0 = fmaxf(m0r, mx0);
        const float mn1 = fmaxf(m1r, mx1);
        const float al0 = __expf(m0r - mn0);
        const float al1 = __expf(m1r - mn1);

        float s0 = 0.f, s1 = 0.f;
        #pragma unroll
        for (int ni = 0; ni < 8; ni++) {
            sc[ni][0] = __expf(sc[ni][0] - mn0);
            sc[ni][1] = __expf(sc[ni][1] - mn0);
            sc[ni][2] = __expf(sc[ni][2] - mn1);
            sc[ni][3] = __expf(sc[ni][3] - mn1);
            s0 += sc[ni][0] + sc[ni][1];
            s1 += sc[ni][2] + sc[ni][3];
        }
        #pragma unroll
        for (int off = 1; off < 4; off <<= 1) {
            s0 += __shfl_xor_sync(0xffffffffu, s0, off);
            s1 += __shfl_xor_sync(0xffffffffu, s1, off);
        }
        l0 = l0 * al0 + s0;
        l1 = l1 * al1 + s1;
        m0r = mn0; m1r = mn1;

        uint32_t ph[8][2];
        #pragma unroll
        for (int ni = 0; ni < 8; ni++) {
            acc[ni][0] *= al0; acc[ni][1] *= al0;
            acc[ni][2] *= al1; acc[ni][3] *= al1;
            ph[ni][0] = fpack(sc[ni][0], sc[ni][1]);
            ph[ni][1] = fpack(sc[ni][2], sc[ni][3]);
        }

        #pragma unroll
        for (int kk = 0; kk < 4; kk++) {
            uint32_t a[4];
            a[0] = ph[2 * kk][0];
            a[1] = ph[2 * kk][1];
            a[2] = ph[2 * kk + 1][0];
            a[3] = ph[2 * kk + 1][1];
            #pragma unroll
            for (int ni = 0; ni < 8; ni++) {
                uint32_t b[2];
                const int nb = (ni * 8 + g) * HSTR + 8 * kk + tg;
                b[0] = Vs[nb];
                b[1] = Vs[nb + 4];
                mma_fp16(acc[ni], a, b);
            }
        }

        __syncthreads();
        if (kt + 2 < nt) { ISSUE_KV(kt + 2, kt & 1); CPA_COMMIT(); }
    }

    // epilogue: write fp16 packed AO (consumed directly by out-GEMM)
    const float il0 = 1.f / l0;
    const float il1 = 1.f / l1;
    const int b_ = bh >> 4, nh = bh & 15;
    #pragma unroll
    for (int ni = 0; ni < 8; ni++) {
        const int cp = nh * 32 + ni * 4 + tg;    // packed col index
        AOh[(size_t)(b_ * SS + row0) * HP + cp] =
            fpack(acc[ni][0] * il0, acc[ni][1] * il0);
        AOh[(size_t)(b_ * SS + row1) * HP + cp] =
            fpack(acc[ni][2] * il1, acc[ni][3] * il1);
    }
    #undef ISSUE_KV
}

// ---------------- launcher ---------------------------------------------------
extern "C" void kernel_launch(void* const* d_in, const int* in_sizes, int n_in,
                              void* d_out, int out_size)
{
    (void)in_sizes; (void)n_in; (void)out_size;
    const float* hs = (const float*)d_in[0];
    const float* wq = (const float*)d_in[2];
    const float* wk = (const float*)d_in[3];
    const float* wv = (const float*)d_in[4];
    const float* wo = (const float*)d_in[5];
    const int*  pos = (const int*)d_in[6];
    float* out = (float*)d_out;

    float *Q, *K, *V;
    uint32_t *Hh, *Wqh, *Wkh, *Wvh, *Woh, *AOh, *Qh, *Kh, *Vh;
    cudaGetSymbolAddress((void**)&Q,   g_Q);
    cudaGetSymbolAddress((void**)&K,   g_K);
    cudaGetSymbolAddress((void**)&V,   g_V);
    cudaGetSymbolAddress((void**)&Hh,  g_Hh);
    cudaGetSymbolAddress((void**)&Wqh, g_Wqh);
    cudaGetSymbolAddress((void**)&Wkh, g_Wkh);
    cudaGetSymbolAddress((void**)&Wvh, g_Wvh);
    cudaGetSymbolAddress((void**)&Woh, g_Woh);
    cudaGetSymbolAddress((void**)&AOh, g_AOh);
    cudaGetSymbolAddress((void**)&Qh,  g_Qh);
    cudaGetSymbolAddress((void**)&Kh,  g_Kh);
    cudaGetSymbolAddress((void**)&Vh,  g_Vh);

    static bool attr_done = false;
    if (!attr_done) {
        cudaFuncSetAttribute(gemm_v4<0>,
                             cudaFuncAttributeMaxDynamicSharedMemorySize, GEMM_SMEM);
        cudaFuncSetAttribute(gemm_v4<1>,
                             cudaFuncAttributeMaxDynamicSharedMemorySize, GEMM_SMEM);
        cudaFuncSetAttribute(flash_fp16,
                             cudaFuncAttributeMaxDynamicSharedMemorySize, FLASH_SMEM);
        attr_done = true;
    }

    // pre-pass: fp32 -> fp16 packed
    pack_fp16<<<1024, 256>>>(hs, Hh, MM * HP);
    pack_fp16<<<512, 256>>>(wq, Wqh, HH * HP);
    pack_fp16<<<512, 256>>>(wk, Wkh, HH * HP);
    pack_fp16<<<512, 256>>>(wv, Wvh, HH * HP);
    pack_fp16<<<512, 256>>>(wo, Woh, HH * HP);

    // QKV fused
    gemm_v4<0><<<dim3(HH/GTN, MM/GTM, 3), 256, GEMM_SMEM>>>(Hh, Wqh, Wkh, Wvh, Q, K, V);

    prep_qk<<<dim3(SS/32, BB*NHH), 256>>>(Q, K, pos, Qh, Kh);
    prep_v<<<dim3(SS/64, BB*NHH), 256>>>(V, Vh);

    flash_fp16<<<dim3(SS/FQ, BB*NHH), 256, FLASH_SMEM>>>(Qh, Kh, Vh, AOh);

    gemm_v4<1><<<dim3(HH/GTN, MM/GTM, 1), 256, GEMM_SMEM>>>(AOh, Woh, Woh, Woh, out, out, out);
}

// round 9
// speedup vs baseline: 2.3893x; 1.0141x over previous
#include <cuda_runtime.h>
#include <cuda_fp16.h>
#include <cstdint>
#include <math.h>

#define BB 2
#define SS 2048
#define HH 1024
#define NHH 16
#define HDD 64
#define MM (BB*SS)   // 4096
#define HP (HH/2)    // 512 u32 per packed row

// ---------------- scratch (allocation-free: device globals) ----------------
__device__ uint32_t g_Hh [MM*HP];                 // hs fp16 packed
__device__ uint32_t g_Wqh[HH*HP];
__device__ uint32_t g_Wkh[HH*HP];
__device__ uint32_t g_Wvh[HH*HP];
__device__ uint32_t g_Woh[HH*HP];
__device__ uint32_t g_AOh[MM*HP];                 // attention out fp16 packed
__device__ uint32_t g_Qh[BB*NHH*SS*(HDD/2)];      // fp16 pairs along d (RoPE'd, *0.125)
__device__ uint32_t g_Kh[BB*NHH*SS*(HDD/2)];      // fp16 pairs along d (RoPE'd)
__device__ uint32_t g_Vt[BB*NHH*SS*(HDD/2)];      // fp16 pairs along d (untransposed)
__device__ uint32_t g_Vh[BB*NHH*HDD*(SS/2)];      // [bh][d][s-pair]
__device__ float2   g_tab[SS*32];                 // (cos, sin) per (pos, i)

// ---------------- helpers ----------------------------------------------------
__device__ __forceinline__ uint32_t fpack(float a, float b) {
    __half2 h = __floats2half2_rn(a, b);
    return *reinterpret_cast<uint32_t*>(&h);
}

__device__ __forceinline__ void mma_fp16(float c[4], const uint32_t a[4], const uint32_t b[2]) {
    asm volatile(
        "mma.sync.aligned.m16n8k16.row.col.f32.f16.f16.f32 "
        "{%0,%1,%2,%3}, {%4,%5,%6,%7}, {%8,%9}, {%0,%1,%2,%3};"
        : "+f"(c[0]), "+f"(c[1]), "+f"(c[2]), "+f"(c[3])
        : "r"(a[0]), "r"(a[1]), "r"(a[2]), "r"(a[3]),
          "r"(b[0]), "r"(b[1]));
}

__device__ __forceinline__ uint32_t smem_u32(const void* p) {
    uint32_t a;
    asm("{ .reg .u64 t; cvta.to.shared.u64 t, %1; cvt.u32.u64 %0, t; }" : "=r"(a) : "l"(p));
    return a;
}

#define CPA16(dst, src) \
    asm volatile("cp.async.cg.shared.global [%0], [%1], 16;" :: "r"(dst), "l"(src))
#define CPA_COMMIT() asm volatile("cp.async.commit_group;" ::: "memory")
#define CPA_WAIT0()  asm volatile("cp.async.wait_group 0;" ::: "memory")
#define CPA_WAIT1()  asm volatile("cp.async.wait_group 1;" ::: "memory")

// ---------------- fused pack: hs + 4 weights -> fp16 packed -----------------
#define NHS (MM*HP)     // 2M u32
#define NWW (HH*HP)     // 512K u32
__global__ void __launch_bounds__(256) pack_all(const float* __restrict__ hs,
                                                const float* __restrict__ wq,
                                                const float* __restrict__ wk,
                                                const float* __restrict__ wv,
                                                const float* __restrict__ wo,
                                                uint32_t* __restrict__ Hh,
                                                uint32_t* __restrict__ Wqh,
                                                uint32_t* __restrict__ Wkh,
                                                uint32_t* __restrict__ Wvh,
                                                uint32_t* __restrict__ Woh)
{
    const int total = NHS + 4 * NWW;   // 4M
    int i = blockIdx.x * blockDim.x + threadIdx.x;
    const int stride = gridDim.x * blockDim.x;
    for (; i < total; i += stride) {
        const float* s; uint32_t* d; int idx;
        if (i < NHS) { s = hs; d = Hh; idx = i; }
        else {
            const int j = i - NHS;
            const int wsel = j >> 19;          // /NWW
            idx = j & (NWW - 1);
            switch (wsel) {
                case 0: s = wq; d = Wqh; break;
                case 1: s = wk; d = Wkh; break;
                case 2: s = wv; d = Wvh; break;
                default: s = wo; d = Woh; break;
            }
        }
        float2 v = ((const float2*)s)[idx];
        d[idx] = fpack(v.x, v.y);
    }
}

// ---------------- rope table: (cos, sin) for pos 0..SS-1, i 0..31 -----------
__global__ void __launch_bounds__(256) rope_table(float2* __restrict__ tab)
{
    const int t = blockIdx.x * blockDim.x + threadIdx.x;   // 65536
    const int p = t >> 5, i = t & 31;
    const float inv = expf(-(float)i * (logf(10000.0f) / 32.0f));
    float sn, cs;
    sincosf((float)p * inv, &sn, &cs);
    tab[t] = make_float2(cs, sn);
}

// ---------------- GEMM v5: fp16 streams, cp.async 3-stage -------------------
// MODE 0: QKV fused (z: 0=Q RoPE+scale, 1=K RoPE, 2=V) -> packed fp16 [bh][s][32]
// MODE 1: row-major fp32 [m*HH + o]
#define GTM 128
#define GTN 256
#define GSTR 20
#define GSTAGE ((GTM + GTN) * GSTR)     // 7680 u32
static const int GEMM_SMEM = 3 * GSTAGE * (int)sizeof(uint32_t);  // 92160

template<int MODE>
__global__ void __launch_bounds__(256, 1) gemm_v5(const uint32_t* __restrict__ A,
                                                  const uint32_t* __restrict__ B0,
                                                  const uint32_t* __restrict__ B1,
                                                  const uint32_t* __restrict__ B2,
                                                  void* __restrict__ Y0v,
                                                  void* __restrict__ Y1v,
                                                  void* __restrict__ Y2v,
                                                  const float2* __restrict__ tab,
                                                  const int* __restrict__ pos_ids)
{
    extern __shared__ uint32_t sm4[];
    const int z = blockIdx.z;
    const uint32_t* Bp = (z == 0) ? B0 : (z == 1) ? B1 : B2;
    void* Yv           = (z == 0) ? Y0v : (z == 1) ? Y1v : Y2v;

    const int tid  = threadIdx.x;
    const int w    = tid >> 5;
    const int lane = tid & 31;
    const int g    = lane >> 2;
    const int tg   = lane & 3;
    const int wm   = (w & 1) * 64;
    const int wn   = (w >> 1) * 64;
    const int m0   = blockIdx.y * GTM;
    const int n0   = blockIdx.x * GTN;
    const uint32_t sb = smem_u32(sm4);

    #define ISSUE_G(IT, STG)                                                      \
        _Pragma("unroll")                                                         \
        for (int i = 0; i < 6; i++) {                                             \
            const int c = tid + i * 256;                                          \
            const int row = c >> 2, j = c & 3;                                    \
            const uint32_t* src = (row < GTM)                                     \
                ? A  + (size_t)(m0 + row)       * HP + (IT) * 16 + j * 4          \
                : Bp + (size_t)(n0 + row - GTM) * HP + (IT) * 16 + j * 4;         \
            CPA16(sb + ((STG) * GSTAGE + row * GSTR + j * 4) * 4, src);           \
        }

    ISSUE_G(0, 0); CPA_COMMIT();
    ISSUE_G(1, 1); CPA_COMMIT();

    float acc[4][8][4];
    #pragma unroll
    for (int mi = 0; mi < 4; mi++)
        #pragma unroll
        for (int ni = 0; ni < 8; ni++)
            #pragma unroll
            for (int r = 0; r < 4; r++) acc[mi][ni][r] = 0.f;

    const int NIT = HP / 16;             // 32
    #pragma unroll 1
    for (int it = 0; it < NIT; it++) {
        if (it < NIT - 1) { CPA_WAIT1(); } else { CPA_WAIT0(); }
        __syncthreads();
        if (it + 2 < NIT) {
            const int stg = (it + 2) % 3;
            ISSUE_G(it + 2, stg);
            CPA_COMMIT();
        }

        const uint32_t* cS = sm4 + (it % 3) * GSTAGE;
        const uint32_t* cB = cS + GTM * GSTR;

        #pragma unroll
        for (int kk = 0; kk < 2; kk++) {
            const int kc = kk * 8;
            uint32_t a[4][4], b[8][2];
            #pragma unroll
            for (int mi = 0; mi < 4; mi++) {
                const int r0 = (wm + 16 * mi + g) * GSTR + kc;
                const int r8 = r0 + 8 * GSTR;
                a[mi][0] = cS[r0 + tg];
                a[mi][1] = cS[r8 + tg];
                a[mi][2] = cS[r0 + tg + 4];
                a[mi][3] = cS[r8 + tg + 4];
            }
            #pragma unroll
            for (int ni = 0; ni < 8; ni++) {
                const int rb = (wn + 8 * ni + g) * GSTR + kc;
                b[ni][0] = cB[rb + tg];
                b[ni][1] = cB[rb + tg + 4];
            }
            #pragma unroll
            for (int mi = 0; mi < 4; mi++)
                #pragma unroll
                for (int ni = 0; ni < 8; ni++)
                    mma_fp16(acc[mi][ni], a[mi], b[ni]);
        }
        __syncthreads();
    }

    if (MODE == 0) {
        // packed fp16 out, per-warp head nh, RoPE for z<2
        uint32_t* Yh = (uint32_t*)Yv;
        const int nh = (n0 + wn) >> 6;
        const float qsc = (z == 0) ? 0.125f : 1.0f;
        #pragma unroll
        for (int mi = 0; mi < 4; mi++) {
            #pragma unroll
            for (int half = 0; half < 2; half++) {
                const int row = m0 + wm + 16 * mi + g + 8 * half;
                const int k0  = 2 * half;              // acc idx 0/1 or 2/3
                const int b_  = row >> 11;
                const int s   = row & (SS - 1);
                const size_t ob = ((size_t)(b_ * NHH + nh) * SS + s) * 32;
                if (z < 2) {
                    int p = pos_ids[b_ * SS + s];
                    p = min(max(p, 0), SS - 1);
                    const float2* tb = tab + p * 32;
                    #pragma unroll
                    for (int ni = 0; ni < 4; ni++) {
                        const int i0 = 8 * ni + 2 * tg;
                        const float2 t0 = tb[i0];
                        const float2 t1 = tb[i0 + 1];
                        const float lo0 = acc[mi][ni][k0],     lo1 = acc[mi][ni][k0 + 1];
                        const float hi0 = acc[mi][ni + 4][k0], hi1 = acc[mi][ni + 4][k0 + 1];
                        const float nl0 = (lo0 * t0.x - hi0 * t0.y) * qsc;
                        const float nl1 = (lo1 * t1.x - hi1 * t1.y) * qsc;
                        const float nh0 = (hi0 * t0.x + lo0 * t0.y) * qsc;
                        const float nh1 = (hi1 * t1.x + lo1 * t1.y) * qsc;
                        Yh[ob + 4 * ni + tg]      = fpack(nl0, nl1);
                        Yh[ob + 16 + 4 * ni + tg] = fpack(nh0, nh1);
                    }
                } else {
                    #pragma unroll
                    for (int ni = 0; ni < 8; ni++)
                        Yh[ob + 4 * ni + tg] = fpack(acc[mi][ni][k0], acc[mi][ni][k0 + 1]);
                }
            }
        }
    } else {
        float* Y = (float*)Yv;
        #pragma unroll
        for (int mi = 0; mi < 4; mi++) {
            #pragma unroll
            for (int ni = 0; ni < 8; ni++) {
                const int row = m0 + wm + 16 * mi + g;
                const int col = n0 + wn + 8 * ni + 2 * tg;
                *(float2*)&Y[(size_t)row * HH + col] =
                    make_float2(acc[mi][ni][0], acc[mi][ni][1]);
                *(float2*)&Y[(size_t)(row + 8) * HH + col] =
                    make_float2(acc[mi][ni][2], acc[mi][ni][3]);
            }
        }
    }
    #undef ISSUE_G
}

// ---------------- prep_v2: fp16 [bh][s][dp] -> fp16 [bh][d][sp] --------------
// grid (SS/64, BB*NHH), block 256; pure integer transpose via smem
__global__ void __launch_bounds__(256) prep_v2(const uint32_t* __restrict__ Vt,
                                               uint32_t* __restrict__ Vh)
{
    __shared__ uint32_t vs[64 * 36];
    const int tid = threadIdx.x;
    const int bh  = blockIdx.y;
    const int st  = blockIdx.x * 64;
    const uint32_t* src = Vt + ((size_t)bh * SS + st) * 32;

    #pragma unroll
    for (int i = 0; i < 2; i++) {
        const int c = tid + i * 256;             // 512 uint4 chunks
        const int row = c >> 3, j = c & 7;
        uint4 v = *(const uint4*)&src[(size_t)row * 32 + j * 4];
        *(uint4*)&vs[row * 36 + j * 4] = v;
    }
    __syncthreads();

    const int d  = tid & 63;
    const int dp = d >> 1;
    const int sh = (d & 1) * 16;
    #pragma unroll
    for (int i = 0; i < 2; i++) {
        const int q = (tid >> 6) + i * 4;        // 0..7
        uint32_t o[4];
        #pragma unroll
        for (int k = 0; k < 4; k++) {
            const int sp = 4 * q + k;
            const uint32_t w0 = vs[(2 * sp) * 36 + dp];
            const uint32_t w1 = vs[(2 * sp + 1) * 36 + dp];
            o[k] = ((w0 >> sh) & 0xffffu) | (((w1 >> sh) & 0xffffu) << 16);
        }
        *(uint4*)&Vh[((size_t)bh * HDD + d) * (SS / 2) + (st >> 1) + 4 * q] =
            make_uint4(o[0], o[1], o[2], o[3]);
    }
}

// ---------------- flash attention: fp16 MMA, P in registers, cp.async -------
#define FQ 128
#define FK 64
#define HSTR 36
#define SQ_OFF 0
#define SK_OFF (FQ * HSTR)
#define STG_SZ (FK * HSTR * 2)
static const int FLASH_SMEM = (FQ * HSTR + 2 * STG_SZ) * (int)sizeof(uint32_t);  // 55296

__global__ void __launch_bounds__(256, 2) flash_fp16(const uint32_t* __restrict__ Qh,
                                                     const uint32_t* __restrict__ Kh,
                                                     const uint32_t* __restrict__ Vh,
                                                     uint32_t* __restrict__ AOh)
{
    extern __shared__ uint32_t fsm[];
    const uint32_t sb = smem_u32(fsm);

    const int tid  = threadIdx.x;
    const int w    = tid >> 5;
    const int lane = tid & 31;
    const int g    = lane >> 2;
    const int tg   = lane & 3;
    const int bh   = blockIdx.y;
    const int qt   = (int)(gridDim.x - 1) - (int)blockIdx.x;
    const int q0   = qt * FQ;

    const uint32_t* qsrc = Qh + ((size_t)bh * SS + q0) * 32;
    const uint32_t* ksrc = Kh + (size_t)bh * SS * 32;
    const uint32_t* vsrc = Vh + (size_t)bh * HDD * (SS / 2);

    const int nt = 2 * qt + 2;

    #define ISSUE_KV(KT, STG)                                                     \
        {                                                                         \
            _Pragma("unroll")                                                     \
            for (int i = 0; i < 2; i++) {                                         \
                const int c = tid + i * 256;                                      \
                const int row = c >> 3, j = c & 7;                                \
                CPA16(sb + (SK_OFF + (STG) * STG_SZ + row * HSTR + j * 4) * 4,    \
                      ksrc + ((size_t)(KT) * FK + row) * 32 + j * 4);             \
            }                                                                     \
            _Pragma("unroll")                                                     \
            for (int i = 0; i < 2; i++) {                                         \
                const int c = tid + i * 256;                                      \
                const int d = c >> 3, j = c & 7;                                  \
                CPA16(sb + (SK_OFF + (STG) * STG_SZ + FK * HSTR + d * HSTR + j * 4) * 4, \
                      vsrc + (size_t)d * (SS / 2) + (KT) * 32 + j * 4);           \
            }                                                                     \
        }

    #pragma unroll
    for (int i = 0; i < 4; i++) {
        const int c = tid + i * 256;
        const int row = c >> 3, j = c & 7;
        CPA16(sb + (SQ_OFF + row * HSTR + j * 4) * 4, qsrc + (size_t)row * 32 + j * 4);
    }
    ISSUE_KV(0, 0);
    CPA_COMMIT();
    if (nt > 1) { ISSUE_KV(1, 1); CPA_COMMIT(); }

    float m0r = -1e30f, m1r = -1e30f, l0 = 0.f, l1 = 0.f;
    float acc[8][4];
    #pragma unroll
    for (int ni = 0; ni < 8; ni++)
        #pragma unroll
        for (int r = 0; r < 4; r++) acc[ni][r] = 0.f;

    const int rloc0 = w * 16 + g;
    const int row0  = q0 + rloc0;
    const int row1  = row0 + 8;

    const uint32_t* Qs = fsm;

    #pragma unroll 1
    for (int kt = 0; kt < nt; kt++) {
        if (kt + 1 < nt) { CPA_WAIT1(); } else { CPA_WAIT0(); }
        __syncthreads();

        const uint32_t* Ks = fsm + SK_OFF + (kt & 1) * STG_SZ;
        const uint32_t* Vs = Ks + FK * HSTR;
        const int k0 = kt * FK;

        float sc[8][4];
        #pragma unroll
        for (int ni = 0; ni < 8; ni++)
            #pragma unroll
            for (int r = 0; r < 4; r++) sc[ni][r] = 0.f;

        #pragma unroll
        for (int kk = 0; kk < 4; kk++) {
            uint32_t a[4];
            const int r0b = rloc0 * HSTR + 8 * kk + tg;
            a[0] = Qs[r0b];
            a[1] = Qs[r0b + 8 * HSTR];
            a[2] = Qs[r0b + 4];
            a[3] = Qs[r0b + 8 * HSTR + 4];
            #pragma unroll
            for (int ni = 0; ni < 8; ni++) {
                uint32_t b[2];
                const int nb = (ni * 8 + g) * HSTR + 8 * kk + tg;
                b[0] = Ks[nb];
                b[1] = Ks[nb + 4];
                mma_fp16(sc[ni], a, b);
            }
        }

        if (kt >= 2 * qt) {
            #pragma unroll
            for (int ni = 0; ni < 8; ni++) {
                const int c = k0 + ni * 8 + 2 * tg;
                if (c     > row0) sc[ni][0] = -1e30f;
                if (c + 1 > row0) sc[ni][1] = -1e30f;
                if (c     > row1) sc[ni][2] = -1e30f;
                if (c + 1 > row1) sc[ni][3] = -1e30f;
            }
        }

        float mx0 = -1e30f, mx1 = -1e30f;
        #pragma unroll
        for (int ni = 0; ni < 8; ni++) {
            mx0 = fmaxf(mx0, fmaxf(sc[ni][0], sc[ni][1]));
            mx1 = fmaxf(mx1, fmaxf(sc[ni][2], sc[ni][3]));
        }
        #pragma unroll
        for (int off = 1; off < 4; off <<= 1) {
            mx0 = fmaxf(mx0, __shfl_xor_sync(0xffffffffu, mx0, off));
            mx1 = fmaxf(mx1, __shfl_xor_sync(0xffffffffu, mx1, off));
        }
        const float mn0 = fmaxf(m0r, mx0);
        const float mn1 = fmaxf(m1r, mx1);
        const float al0 = __expf(m0r - mn0);
        const float al1 = __expf(m1r - mn1);

        float s0 = 0.f, s1 = 0.f;
        #pragma unroll
        for (int ni = 0; ni < 8; ni++) {
            sc[ni][0] = __expf(sc[ni][0] - mn0);
            sc[ni][1] = __expf(sc[ni][1] - mn0);
            sc[ni][2] = __expf(sc[ni][2] - mn1);
            sc[ni][3] = __expf(sc[ni][3] - mn1);
            s0 += sc[ni][0] + sc[ni][1];
            s1 += sc[ni][2] + sc[ni][3];
        }
        #pragma unroll
        for (int off = 1; off < 4; off <<= 1) {
            s0 += __shfl_xor_sync(0xffffffffu, s0, off);
            s1 += __shfl_xor_sync(0xffffffffu, s1, off);
        }
        l0 = l0 * al0 + s0;
        l1 = l1 * al1 + s1;
        m0r = mn0; m1r = mn1;

        uint32_t ph[8][2];
        #pragma unroll
        for (int ni = 0; ni < 8; ni++) {
            acc[ni][0] *= al0; acc[ni][1] *= al0;
            acc[ni][2] *= al1; acc[ni][3] *= al1;
            ph[ni][0] = fpack(sc[ni][0], sc[ni][1]);
            ph[ni][1] = fpack(sc[ni][2], sc[ni][3]);
        }

        #pragma unroll
        for (int kk = 0; kk < 4; kk++) {
            uint32_t a[4];
            a[0] = ph[2 * kk][0];
            a[1] = ph[2 * kk][1];
            a[2] = ph[2 * kk + 1][0];
            a[3] = ph[2 * kk + 1][1];
            #pragma unroll
            for (int ni = 0; ni < 8; ni++) {
                uint32_t b[2];
                const int nb = (ni * 8 + g) * HSTR + 8 * kk + tg;
                b[0] = Vs[nb];
                b[1] = Vs[nb + 4];
                mma_fp16(acc[ni], a, b);
            }
        }

        __syncthreads();
        if (kt + 2 < nt) { ISSUE_KV(kt + 2, kt & 1); CPA_COMMIT(); }
    }

    const float il0 = 1.f / l0;
    const float il1 = 1.f / l1;
    const int b_ = bh >> 4, nh = bh & 15;
    #pragma unroll
    for (int ni = 0; ni < 8; ni++) {
        const int cp = nh * 32 + ni * 4 + tg;
        AOh[(size_t)(b_ * SS + row0) * HP + cp] =
            fpack(acc[ni][0] * il0, acc[ni][1] * il0);
        AOh[(size_t)(b_ * SS + row1) * HP + cp] =
            fpack(acc[ni][2] * il1, acc[ni][3] * il1);
    }
    #undef ISSUE_KV
}

// ---------------- launcher ---------------------------------------------------
extern "C" void kernel_launch(void* const* d_in, const int* in_sizes, int n_in,
                              void* d_out, int out_size)
{
    (void)in_sizes; (void)n_in; (void)out_size;
    const float* hs = (const float*)d_in[0];
    const float* wq = (const float*)d_in[2];
    const float* wk = (const float*)d_in[3];
    const float* wv = (const float*)d_in[4];
    const float* wo = (const float*)d_in[5];
    const int*  pos = (const int*)d_in[6];
    float* out = (float*)d_out;

    uint32_t *Hh, *Wqh, *Wkh, *Wvh, *Woh, *AOh, *Qh, *Kh, *Vt, *Vh;
    float2* tab;
    cudaGetSymbolAddress((void**)&Hh,  g_Hh);
    cudaGetSymbolAddress((void**)&Wqh, g_Wqh);
    cudaGetSymbolAddress((void**)&Wkh, g_Wkh);
    cudaGetSymbolAddress((void**)&Wvh, g_Wvh);
    cudaGetSymbolAddress((void**)&Woh, g_Woh);
    cudaGetSymbolAddress((void**)&AOh, g_AOh);
    cudaGetSymbolAddress((void**)&Qh,  g_Qh);
    cudaGetSymbolAddress((void**)&Kh,  g_Kh);
    cudaGetSymbolAddress((void**)&Vt,  g_Vt);
    cudaGetSymbolAddress((void**)&Vh,  g_Vh);
    cudaGetSymbolAddress((void**)&tab, g_tab);

    static bool attr_done = false;
    if (!attr_done) {
        cudaFuncSetAttribute(gemm_v5<0>,
                             cudaFuncAttributeMaxDynamicSharedMemorySize, GEMM_SMEM);
        cudaFuncSetAttribute(gemm_v5<1>,
                             cudaFuncAttributeMaxDynamicSharedMemorySize, GEMM_SMEM);
        cudaFuncSetAttribute(flash_fp16,
                             cudaFuncAttributeMaxDynamicSharedMemorySize, FLASH_SMEM);
        attr_done = true;
    }

    rope_table<<<256, 256>>>(tab);
    pack_all<<<1024, 256>>>(hs, wq, wk, wv, wo, Hh, Wqh, Wkh, Wvh, Woh);

    // QKV fused, RoPE + fp16 pack in epilogue
    gemm_v5<0><<<dim3(HH/GTN, MM/GTM, 3), 256, GEMM_SMEM>>>(
        Hh, Wqh, Wkh, Wvh, Qh, Kh, Vt, tab, pos);

    prep_v2<<<dim3(SS/64, BB*NHH), 256>>>(Vt, Vh);

    flash_fp16<<<dim3(SS/FQ, BB*NHH), 256, FLASH_SMEM>>>(Qh, Kh, Vh, AOh);

    gemm_v5<1><<<dim3(HH/GTN, MM/GTM, 1), 256, GEMM_SMEM>>>(
        AOh, Woh, Woh, Woh, out, out, out, tab, pos);
}